// round 2
// baseline (speedup 1.0000x reference)
#include <cuda_runtime.h>
#include <math.h>

#define B_   2
#define L_   2048
#define DM   1024
#define DI   2048
#define DS   16
#define DTR  64
#define BL   (B_*L_)   /* 4096 rows */

// ---------------- scratch (static device allocs; no cudaMalloc allowed) ----
__device__ float g_res  [(size_t)BL*DM];      // sanitized residual
__device__ float g_xn   [(size_t)BL*DM];      // layernorm output
__device__ float g_xz   [(size_t)BL*2*DI];    // in_proj output (u_raw | z)
__device__ float g_u    [(size_t)BL*DI];      // conv+silu output
__device__ float g_xdbl [(size_t)BL*96];      // x_proj output (dt|B|C)
__device__ float g_delta[(size_t)BL*DI];      // softplus(dt_proj)
__device__ float g_y    [(size_t)BL*DI];      // gated scan output

__device__ __forceinline__ float sanit(float v) {
    if (isnan(v)) return 0.f;
    if (isinf(v)) return v > 0.f ? 1e4f : -1e4f;
    return v;
}

// ---------------- LayerNorm (one block per row) ----------------------------
__global__ void ln_kernel(const float* __restrict__ x,
                          const float* __restrict__ g,
                          const float* __restrict__ b) {
    int row = blockIdx.x;
    int tid = threadIdx.x;
    const float* xr = x + (size_t)row * DM;
    float v[4];
    float s = 0.f, s2 = 0.f;
#pragma unroll
    for (int i = 0; i < 4; i++) {
        float t = sanit(xr[tid + i * 256]);
        v[i] = t; s += t; s2 += t * t;
    }
#pragma unroll
    for (int o = 16; o; o >>= 1) {
        s  += __shfl_xor_sync(0xffffffffu, s,  o);
        s2 += __shfl_xor_sync(0xffffffffu, s2, o);
    }
    __shared__ float ss[8], ss2[8], smu, srs;
    int w = tid >> 5, ln = tid & 31;
    if (ln == 0) { ss[w] = s; ss2[w] = s2; }
    __syncthreads();
    if (tid == 0) {
        float a = 0.f, a2 = 0.f;
#pragma unroll
        for (int i = 0; i < 8; i++) { a += ss[i]; a2 += ss2[i]; }
        float mu = a / DM;
        float var = fmaxf(a2 / DM - mu * mu, 0.f);
        smu = mu;
        srs = rsqrtf(var + 1e-5f);
    }
    __syncthreads();
    float mu = smu, rs = srs;
#pragma unroll
    for (int i = 0; i < 4; i++) {
        int c = tid + i * 256;
        g_res[(size_t)row * DM + c] = v[i];
        g_xn [(size_t)row * DM + c] = (v[i] - mu) * rs * g[c] + b[c];
    }
}

// ---------------- generic fp32 GEMM:  C[M,N] = A[M,K(lda)] * B[N,K(ldb)]^T --
// epi: 0 = plain store, 1 = +bias then softplus, 2 = sanitize + residual add
__global__ void gemm_kernel(const float* __restrict__ A, int lda,
                            const float* __restrict__ Bm, int ldb,
                            float* __restrict__ C,
                            int M, int N, int K,
                            int epi,
                            const float* __restrict__ bias,
                            const float* __restrict__ res) {
    __shared__ float As[16][65];
    __shared__ float Bs[16][65];
    int bm = blockIdx.y * 64, bn = blockIdx.x * 64;
    int tid = threadIdx.x;
    int lk = tid & 15, lr = tid >> 4;
    int trow = (tid >> 4) << 2;
    int tcol = (tid & 15) << 2;
    float acc[4][4] = {};

    for (int k0 = 0; k0 < K; k0 += 16) {
#pragma unroll
        for (int i = 0; i < 4; i++) {
            int m = bm + lr + i * 16;
            As[lk][lr + i * 16] = (m < M) ? A[(size_t)m * lda + k0 + lk] : 0.f;
            int n = bn + lr + i * 16;
            Bs[lk][lr + i * 16] = (n < N) ? Bm[(size_t)n * ldb + k0 + lk] : 0.f;
        }
        __syncthreads();
#pragma unroll
        for (int kk = 0; kk < 16; kk++) {
            float a[4], bb[4];
#pragma unroll
            for (int i = 0; i < 4; i++) a[i]  = As[kk][trow + i];
#pragma unroll
            for (int j = 0; j < 4; j++) bb[j] = Bs[kk][tcol + j];
#pragma unroll
            for (int i = 0; i < 4; i++)
#pragma unroll
                for (int j = 0; j < 4; j++)
                    acc[i][j] = fmaf(a[i], bb[j], acc[i][j]);
        }
        __syncthreads();
    }

#pragma unroll
    for (int i = 0; i < 4; i++) {
        int m = bm + trow + i;
        if (m >= M) continue;
#pragma unroll
        for (int j = 0; j < 4; j++) {
            int n = bn + tcol + j;
            if (n >= N) continue;
            float v = acc[i][j];
            if (epi == 1) {
                v += bias[n];
                v = (v > 20.f) ? v : log1pf(__expf(v));
            } else if (epi == 2) {
                v = sanit(v);
                v = sanit(res[(size_t)m * N + n] + v);
            }
            C[(size_t)m * N + n] = v;
        }
    }
}

// ---------------- causal depthwise conv (k=4) + SiLU -----------------------
__global__ void conv_silu_kernel(const float* __restrict__ cw,
                                 const float* __restrict__ cb) {
    int idx = blockIdx.x * blockDim.x + threadIdx.x;  // over BL*DI
    if (idx >= BL * DI) return;
    int d   = idx & (DI - 1);
    int row = idx >> 11;            // b*L + l
    int l   = row & (L_ - 1);
    float acc = cb[d];
#pragma unroll
    for (int k = 0; k < 4; k++) {
        int ll = l - 3 + k;
        if (ll >= 0)
            acc = fmaf(g_xz[(size_t)(row - 3 + k) * (2 * DI) + d], cw[d * 4 + k], acc);
    }
    acc = acc / (1.f + __expf(-acc));   // silu
    g_u[idx] = acc;
}

// ---------------- selective scan + D-skip + gate ----------------------------
// thread = (b, d, n) : 2 * 2048 * 16 = 65536 threads. 16-lane shuffle reduce
// for y = C . h ; lane n==0 of each channel writes gated output.
__global__ void scan_kernel(const float* __restrict__ A_log,
                            const float* __restrict__ D_skip) {
    int gt = blockIdx.x * blockDim.x + threadIdx.x;   // 0..65535
    int n  = gt & 15;
    int d  = (gt >> 4) & (DI - 1);
    int b  = gt >> 15;

    float Aneg = -__expf(A_log[d * DS + n]);
    float Dv   = D_skip[d];
    float h    = 0.f;
    bool head  = (n == 0);

    const float* xd = g_xdbl + (size_t)b * L_ * 96;
    size_t rowbase = (size_t)b * L_;

    for (int t = 0; t < L_; t++) {
        size_t row = rowbase + t;
        float dt = g_delta[row * DI + d];
        float ut = g_u    [row * DI + d];
        float Bt = xd[t * 96 + 64 + n];
        float Ct = xd[t * 96 + 80 + n];

        float dA = __expf(dt * Aneg);
        h = fmaf(dA, h, (dt * ut) * Bt);

        float p = h * Ct;
        p += __shfl_xor_sync(0xffffffffu, p, 1);
        p += __shfl_xor_sync(0xffffffffu, p, 2);
        p += __shfl_xor_sync(0xffffffffu, p, 4);
        p += __shfl_xor_sync(0xffffffffu, p, 8);

        if (head) {
            float z  = g_xz[row * (2 * DI) + DI + d];
            float sz = z / (1.f + __expf(-z));
            g_y[row * DI + d] = (p + ut * Dv) * sz;
        }
    }
}

// ---------------- launch -----------------------------------------------------
extern "C" void kernel_launch(void* const* d_in, const int* in_sizes, int n_in,
                              void* d_out, int out_size) {
    const float* x         = (const float*)d_in[0];
    const float* ln_g      = (const float*)d_in[1];
    const float* ln_b      = (const float*)d_in[2];
    const float* in_proj_w = (const float*)d_in[3];
    const float* conv_w    = (const float*)d_in[4];
    const float* conv_b    = (const float*)d_in[5];
    const float* x_proj_w  = (const float*)d_in[6];
    const float* dt_proj_w = (const float*)d_in[7];
    const float* dt_proj_b = (const float*)d_in[8];
    const float* A_log     = (const float*)d_in[9];
    const float* D_skip    = (const float*)d_in[10];
    const float* out_proj_w= (const float*)d_in[11];
    float* out = (float*)d_out;

    float *p_xn, *p_xz, *p_u, *p_xdbl, *p_delta, *p_y, *p_res;
    cudaGetSymbolAddress((void**)&p_xn,    g_xn);
    cudaGetSymbolAddress((void**)&p_xz,    g_xz);
    cudaGetSymbolAddress((void**)&p_u,     g_u);
    cudaGetSymbolAddress((void**)&p_xdbl,  g_xdbl);
    cudaGetSymbolAddress((void**)&p_delta, g_delta);
    cudaGetSymbolAddress((void**)&p_y,     g_y);
    cudaGetSymbolAddress((void**)&p_res,   g_res);

    // 1. layernorm (+ residual stash)
    ln_kernel<<<BL, 256>>>(x, ln_g, ln_b);

    // 2. in_proj: [4096,1024] x [4096,1024]^T -> [4096,4096]
    gemm_kernel<<<dim3(64, 64), 256>>>(p_xn, DM, in_proj_w, DM, p_xz,
                                       BL, 2 * DI, DM, 0, nullptr, nullptr);

    // 3. depthwise causal conv + silu -> u
    conv_silu_kernel<<<(BL * DI) / 256, 256>>>(conv_w, conv_b);

    // 4. x_proj: [4096,2048] x [96,2048]^T -> [4096,96]
    gemm_kernel<<<dim3(2, 64), 256>>>(p_u, DI, x_proj_w, DI, p_xdbl,
                                      BL, 96, DI, 0, nullptr, nullptr);

    // 5. dt_proj + softplus: [4096,64(ld 96)] x [2048,64]^T -> delta
    gemm_kernel<<<dim3(32, 64), 256>>>(p_xdbl, 96, dt_proj_w, DTR, p_delta,
                                       BL, DI, DTR, 1, dt_proj_b, nullptr);

    // 6. selective scan + D-skip + silu(z) gate -> y
    scan_kernel<<<256, 256>>>(A_log, D_skip);

    // 7. out_proj + residual + sanitize -> out
    gemm_kernel<<<dim3(16, 64), 256>>>(p_y, DI, out_proj_w, DI, out,
                                       BL, DM, DI, 2, nullptr, p_res);
}

// round 3
// speedup vs baseline: 1.2648x; 1.2648x over previous
#include <cuda_runtime.h>
#include <math.h>

#define B_   2
#define L_   2048
#define DM   1024
#define DI   2048
#define DS   16
#define DTR  64
#define BL   (B_*L_)   /* 4096 rows */

// ---------------- scratch (static device allocs; no cudaMalloc allowed) ----
__device__ float g_res  [(size_t)BL*DM];      // sanitized residual
__device__ float g_xn   [(size_t)BL*DM];      // layernorm output
__device__ float g_xz   [(size_t)BL*2*DI];    // in_proj output (u_raw | z)
__device__ float g_u    [(size_t)BL*DI];      // conv+silu output
__device__ float g_xdbl [(size_t)BL*96];      // x_proj output (dt|B|C)
__device__ float g_delta[(size_t)BL*DI];      // softplus(dt_proj)
__device__ float g_y    [(size_t)BL*DI];      // gated scan output

__device__ __forceinline__ float sanit(float v) {
    if (isnan(v)) return 0.f;
    if (isinf(v)) return v > 0.f ? 1e4f : -1e4f;
    return v;
}

// ---------------- LayerNorm (one block per row) ----------------------------
__global__ void ln_kernel(const float* __restrict__ x,
                          const float* __restrict__ g,
                          const float* __restrict__ b) {
    int row = blockIdx.x;
    int tid = threadIdx.x;
    const float* xr = x + (size_t)row * DM;
    float v[4];
    float s = 0.f, s2 = 0.f;
#pragma unroll
    for (int i = 0; i < 4; i++) {
        float t = sanit(xr[tid + i * 256]);
        v[i] = t; s += t; s2 += t * t;
    }
#pragma unroll
    for (int o = 16; o; o >>= 1) {
        s  += __shfl_xor_sync(0xffffffffu, s,  o);
        s2 += __shfl_xor_sync(0xffffffffu, s2, o);
    }
    __shared__ float ss[8], ss2[8], smu, srs;
    int w = tid >> 5, ln = tid & 31;
    if (ln == 0) { ss[w] = s; ss2[w] = s2; }
    __syncthreads();
    if (tid == 0) {
        float a = 0.f, a2 = 0.f;
#pragma unroll
        for (int i = 0; i < 8; i++) { a += ss[i]; a2 += ss2[i]; }
        float mu = a / DM;
        float var = fmaxf(a2 / DM - mu * mu, 0.f);
        smu = mu;
        srs = rsqrtf(var + 1e-5f);
    }
    __syncthreads();
    float mu = smu, rs = srs;
#pragma unroll
    for (int i = 0; i < 4; i++) {
        int c = tid + i * 256;
        g_res[(size_t)row * DM + c] = v[i];
        g_xn [(size_t)row * DM + c] = (v[i] - mu) * rs * g[c] + b[c];
    }
}

// ---------------- 128x128 tile fp32 GEMM: C[M,N] = A[M,K] * B[N,K]^T -------
// A row-major lda, B row-major ldb (both K-contiguous). M must be mult of 128.
// epi: 0 = plain store, 1 = +bias then softplus, 2 = sanitize + residual add
__global__ void __launch_bounds__(256, 2)
gemm128_kernel(const float* __restrict__ A, int lda,
               const float* __restrict__ Bm, int ldb,
               float* __restrict__ C,
               int M, int N, int K, int epi,
               const float* __restrict__ bias,
               const float* __restrict__ res) {
    __shared__ float As[2][16][132];
    __shared__ float Bs[2][16][132];
    const int bm  = blockIdx.y * 128, bn = blockIdx.x * 128;
    const int tid = threadIdx.x;
    const int lk  = (tid & 3) * 4;      // k offset of this thread's float4
    const int lm  = tid >> 2;           // 0..63 (row within half-tile)
    const int tr4 = (tid >> 4) << 2;    // 0..60
    const int tc4 = (tid & 15) << 2;    // 0..60

    float4 ra[2], rb[2];
    float acc[8][8];
#pragma unroll
    for (int i = 0; i < 8; i++)
#pragma unroll
        for (int j = 0; j < 8; j++) acc[i][j] = 0.f;

    auto gload = [&](int k0) {
#pragma unroll
        for (int i = 0; i < 2; i++) {
            int m = bm + lm + i * 64;
            ra[i] = *(const float4*)(A + (size_t)m * lda + k0 + lk);
            int n = bn + lm + i * 64;
            rb[i] = (n < N) ? *(const float4*)(Bm + (size_t)n * ldb + k0 + lk)
                            : make_float4(0.f, 0.f, 0.f, 0.f);
        }
    };
    auto sstore = [&](int buf) {
#pragma unroll
        for (int i = 0; i < 2; i++) {
            int col = lm + i * 64;
            As[buf][lk + 0][col] = ra[i].x;
            As[buf][lk + 1][col] = ra[i].y;
            As[buf][lk + 2][col] = ra[i].z;
            As[buf][lk + 3][col] = ra[i].w;
            Bs[buf][lk + 0][col] = rb[i].x;
            Bs[buf][lk + 1][col] = rb[i].y;
            Bs[buf][lk + 2][col] = rb[i].z;
            Bs[buf][lk + 3][col] = rb[i].w;
        }
    };
    auto compute = [&](int buf) {
#pragma unroll
        for (int kk = 0; kk < 16; kk++) {
            float4 a0 = *(const float4*)&As[buf][kk][tr4];
            float4 a1 = *(const float4*)&As[buf][kk][tr4 + 64];
            float4 b0 = *(const float4*)&Bs[buf][kk][tc4];
            float4 b1 = *(const float4*)&Bs[buf][kk][tc4 + 64];
            float a[8] = {a0.x, a0.y, a0.z, a0.w, a1.x, a1.y, a1.z, a1.w};
            float bb[8] = {b0.x, b0.y, b0.z, b0.w, b1.x, b1.y, b1.z, b1.w};
#pragma unroll
            for (int i = 0; i < 8; i++)
#pragma unroll
                for (int j = 0; j < 8; j++)
                    acc[i][j] = fmaf(a[i], bb[j], acc[i][j]);
        }
    };

    gload(0);
    sstore(0);
    __syncthreads();
    int buf = 0;
    for (int k0 = 16; k0 < K; k0 += 16) {
        gload(k0);
        compute(buf);
        sstore(buf ^ 1);
        __syncthreads();
        buf ^= 1;
    }
    compute(buf);

    // epilogue: rows {bm + ih*64 + tr4 + ii}, cols {bn + jh*64 + tc4 + jj}
#pragma unroll
    for (int ih = 0; ih < 2; ih++)
#pragma unroll
        for (int ii = 0; ii < 4; ii++) {
            int m = bm + ih * 64 + tr4 + ii;
#pragma unroll
            for (int jh = 0; jh < 2; jh++)
#pragma unroll
                for (int jj = 0; jj < 4; jj++) {
                    int n = bn + jh * 64 + tc4 + jj;
                    if (n >= N) continue;
                    float v = acc[ih * 4 + ii][jh * 4 + jj];
                    if (epi == 1) {
                        v += bias[n];
                        v = (v > 20.f) ? v : log1pf(__expf(v));
                    } else if (epi == 2) {
                        v = sanit(v);
                        v = sanit(res[(size_t)m * N + n] + v);
                    }
                    C[(size_t)m * N + n] = v;
                }
        }
}

// ---------------- 64x64 tile split-K GEMM (for x_proj, N=96) ----------------
// C += A[M, kb:ke] * B[N, kb:ke]^T  via atomicAdd (C pre-zeroed).
__global__ void gemm64sk_kernel(const float* __restrict__ A, int lda,
                                const float* __restrict__ Bm, int ldb,
                                float* __restrict__ C,
                                int M, int N, int kchunk) {
    __shared__ float As[16][65];
    __shared__ float Bs[16][65];
    int bm = blockIdx.y * 64, bn = blockIdx.x * 64;
    int kb = blockIdx.z * kchunk;
    int tid = threadIdx.x;
    int lk = tid & 15, lr = tid >> 4;
    int trow = (tid >> 4) << 2;
    int tcol = (tid & 15) << 2;
    float acc[4][4] = {};

    for (int k0 = kb; k0 < kb + kchunk; k0 += 16) {
#pragma unroll
        for (int i = 0; i < 4; i++) {
            int m = bm + lr + i * 16;
            As[lk][lr + i * 16] = A[(size_t)m * lda + k0 + lk];
            int n = bn + lr + i * 16;
            Bs[lk][lr + i * 16] = (n < N) ? Bm[(size_t)n * ldb + k0 + lk] : 0.f;
        }
        __syncthreads();
#pragma unroll
        for (int kk = 0; kk < 16; kk++) {
            float a[4], bb[4];
#pragma unroll
            for (int i = 0; i < 4; i++) a[i]  = As[kk][trow + i];
#pragma unroll
            for (int j = 0; j < 4; j++) bb[j] = Bs[kk][tcol + j];
#pragma unroll
            for (int i = 0; i < 4; i++)
#pragma unroll
                for (int j = 0; j < 4; j++)
                    acc[i][j] = fmaf(a[i], bb[j], acc[i][j]);
        }
        __syncthreads();
    }
#pragma unroll
    for (int i = 0; i < 4; i++) {
        int m = bm + trow + i;
#pragma unroll
        for (int j = 0; j < 4; j++) {
            int n = bn + tcol + j;
            if (n < N)
                atomicAdd(&C[(size_t)m * N + n], acc[i][j]);
        }
    }
}

// ---------------- causal depthwise conv (k=4) + SiLU -----------------------
__global__ void conv_silu_kernel(const float* __restrict__ cw,
                                 const float* __restrict__ cb) {
    int idx = blockIdx.x * blockDim.x + threadIdx.x;  // over BL*DI
    if (idx >= BL * DI) return;
    int d   = idx & (DI - 1);
    int row = idx >> 11;            // b*L + l
    int l   = row & (L_ - 1);
    float acc = cb[d];
#pragma unroll
    for (int k = 0; k < 4; k++) {
        int ll = l - 3 + k;
        if (ll >= 0)
            acc = fmaf(g_xz[(size_t)(row - 3 + k) * (2 * DI) + d], cw[d * 4 + k], acc);
    }
    acc = acc / (1.f + __expf(-acc));   // silu
    g_u[idx] = acc;
}

// ---------------- selective scan + D-skip + gate ----------------------------
__global__ void scan_kernel(const float* __restrict__ A_log,
                            const float* __restrict__ D_skip) {
    int gt = blockIdx.x * blockDim.x + threadIdx.x;   // 0..65535
    int n  = gt & 15;
    int d  = (gt >> 4) & (DI - 1);
    int b  = gt >> 15;

    float Aneg = -__expf(A_log[d * DS + n]);
    float Dv   = D_skip[d];
    float h    = 0.f;
    bool head  = (n == 0);

    const float* xd = g_xdbl + (size_t)b * L_ * 96;
    size_t rowbase = (size_t)b * L_;

    for (int t = 0; t < L_; t++) {
        size_t row = rowbase + t;
        float dt = g_delta[row * DI + d];
        float ut = g_u    [row * DI + d];
        float Bt = xd[t * 96 + 64 + n];
        float Ct = xd[t * 96 + 80 + n];

        float dA = __expf(dt * Aneg);
        h = fmaf(dA, h, (dt * ut) * Bt);

        float p = h * Ct;
        p += __shfl_xor_sync(0xffffffffu, p, 1);
        p += __shfl_xor_sync(0xffffffffu, p, 2);
        p += __shfl_xor_sync(0xffffffffu, p, 4);
        p += __shfl_xor_sync(0xffffffffu, p, 8);

        if (head) {
            float z  = g_xz[row * (2 * DI) + DI + d];
            float sz = z / (1.f + __expf(-z));
            g_y[row * DI + d] = (p + ut * Dv) * sz;
        }
    }
}

// ---------------- launch -----------------------------------------------------
extern "C" void kernel_launch(void* const* d_in, const int* in_sizes, int n_in,
                              void* d_out, int out_size) {
    const float* x         = (const float*)d_in[0];
    const float* ln_g      = (const float*)d_in[1];
    const float* ln_b      = (const float*)d_in[2];
    const float* in_proj_w = (const float*)d_in[3];
    const float* conv_w    = (const float*)d_in[4];
    const float* conv_b    = (const float*)d_in[5];
    const float* x_proj_w  = (const float*)d_in[6];
    const float* dt_proj_w = (const float*)d_in[7];
    const float* dt_proj_b = (const float*)d_in[8];
    const float* A_log     = (const float*)d_in[9];
    const float* D_skip    = (const float*)d_in[10];
    const float* out_proj_w= (const float*)d_in[11];
    float* out = (float*)d_out;

    float *p_xn, *p_xz, *p_u, *p_xdbl, *p_delta, *p_y, *p_res;
    cudaGetSymbolAddress((void**)&p_xn,    g_xn);
    cudaGetSymbolAddress((void**)&p_xz,    g_xz);
    cudaGetSymbolAddress((void**)&p_u,     g_u);
    cudaGetSymbolAddress((void**)&p_xdbl,  g_xdbl);
    cudaGetSymbolAddress((void**)&p_delta, g_delta);
    cudaGetSymbolAddress((void**)&p_y,     g_y);
    cudaGetSymbolAddress((void**)&p_res,   g_res);

    // 1. layernorm (+ residual stash)
    ln_kernel<<<BL, 256>>>(x, ln_g, ln_b);

    // 2. in_proj: [4096,1024] x [4096,1024]^T -> [4096,4096]
    gemm128_kernel<<<dim3(32, 32), 256>>>(p_xn, DM, in_proj_w, DM, p_xz,
                                          BL, 2 * DI, DM, 0, nullptr, nullptr);

    // 3. depthwise causal conv + silu -> u
    conv_silu_kernel<<<(BL * DI) / 256, 256>>>(conv_w, conv_b);

    // 4. x_proj: [4096,2048] x [96,2048]^T -> [4096,96]  (split-K x8, atomic)
    cudaMemsetAsync(p_xdbl, 0, (size_t)BL * 96 * sizeof(float));
    gemm64sk_kernel<<<dim3(2, 64, 8), 256>>>(p_u, DI, x_proj_w, DI, p_xdbl,
                                             BL, 96, DI / 8);

    // 5. dt_proj + softplus: [4096,64(ld 96)] x [2048,64]^T -> delta
    gemm128_kernel<<<dim3(16, 32), 256>>>(p_xdbl, 96, dt_proj_w, DTR, p_delta,
                                          BL, DI, DTR, 1, dt_proj_b, nullptr);

    // 6. selective scan + D-skip + silu(z) gate -> y
    scan_kernel<<<256, 256>>>(A_log, D_skip);

    // 7. out_proj + residual + sanitize -> out
    gemm128_kernel<<<dim3(8, 32), 256>>>(p_y, DI, out_proj_w, DI, out,
                                         BL, DM, DI, 2, nullptr, p_res);
}

// round 4
// speedup vs baseline: 1.4596x; 1.1541x over previous
#include <cuda_runtime.h>
#include <math.h>

#define B_   2
#define L_   2048
#define DM   1024
#define DI   2048
#define DS   16
#define DTR  64
#define BL   (B_*L_)   /* 4096 rows */

// ---------------- scratch ----------------------------------------------------
__device__ float g_res  [(size_t)BL*DM];
__device__ float g_xn   [(size_t)BL*DM];
__device__ float g_xz   [(size_t)BL*2*DI];
__device__ float g_u    [(size_t)BL*DI];
__device__ float g_xdbl [(size_t)BL*96];
__device__ float g_delta[(size_t)BL*DI];
__device__ float g_y    [(size_t)BL*DI];

__device__ __forceinline__ float sanit(float v) {
    if (isnan(v)) return 0.f;
    if (isinf(v)) return v > 0.f ? 1e4f : -1e4f;
    return v;
}

__device__ __forceinline__ unsigned f2tf32(float f) {
    unsigned r;
    asm("cvt.rna.tf32.f32 %0, %1;" : "=r"(r) : "f"(f));
    return r;
}

__device__ __forceinline__ void mma_tf32(float* d, const unsigned* a, const unsigned* b) {
    asm volatile(
        "mma.sync.aligned.m16n8k8.row.col.f32.tf32.tf32.f32 "
        "{%0,%1,%2,%3}, {%4,%5,%6,%7}, {%8,%9}, {%0,%1,%2,%3};"
        : "+f"(d[0]), "+f"(d[1]), "+f"(d[2]), "+f"(d[3])
        : "r"(a[0]), "r"(a[1]), "r"(a[2]), "r"(a[3]), "r"(b[0]), "r"(b[1]));
}

// ---------------- LayerNorm --------------------------------------------------
__global__ void ln_kernel(const float* __restrict__ x,
                          const float* __restrict__ g,
                          const float* __restrict__ b) {
    int row = blockIdx.x;
    int tid = threadIdx.x;
    const float* xr = x + (size_t)row * DM;
    float v[4];
    float s = 0.f, s2 = 0.f;
#pragma unroll
    for (int i = 0; i < 4; i++) {
        float t = sanit(xr[tid + i * 256]);
        v[i] = t; s += t; s2 += t * t;
    }
#pragma unroll
    for (int o = 16; o; o >>= 1) {
        s  += __shfl_xor_sync(0xffffffffu, s,  o);
        s2 += __shfl_xor_sync(0xffffffffu, s2, o);
    }
    __shared__ float ss[8], ss2[8], smu, srs;
    int w = tid >> 5, ln = tid & 31;
    if (ln == 0) { ss[w] = s; ss2[w] = s2; }
    __syncthreads();
    if (tid == 0) {
        float a = 0.f, a2 = 0.f;
#pragma unroll
        for (int i = 0; i < 8; i++) { a += ss[i]; a2 += ss2[i]; }
        float mu = a / DM;
        float var = fmaxf(a2 / DM - mu * mu, 0.f);
        smu = mu;
        srs = rsqrtf(var + 1e-5f);
    }
    __syncthreads();
    float mu = smu, rs = srs;
#pragma unroll
    for (int i = 0; i < 4; i++) {
        int c = tid + i * 256;
        g_res[(size_t)row * DM + c] = v[i];
        g_xn [(size_t)row * DM + c] = (v[i] - mu) * rs * g[c] + b[c];
    }
}

// ---------------- tf32 tensor-core GEMM: C[M,N] = A[M,K] * B[N,K]^T ----------
// M, N multiples of 128; K multiple of 16. A lda, B ldb (both K-contiguous).
// epi: 0 plain, 1 bias+softplus, 2 sanitize+residual
// smem staged in mma fragment order: A [mt(8)][ks(2)][lane(32)][reg(4)]
//                                    B [nt(16)][ks(2)][lane(32)][reg(2)]
__global__ void __launch_bounds__(256)
gemm_tc_kernel(const float* __restrict__ A, int lda,
               const float* __restrict__ Bm, int ldb,
               float* __restrict__ C,
               int M, int N, int K, int epi,
               const float* __restrict__ bias,
               const float* __restrict__ res) {
    __shared__ __align__(16) unsigned As[2][2048];
    __shared__ __align__(16) unsigned Bs[2][2048];

    const int bm = blockIdx.y * 128, bn = blockIdx.x * 128;
    const int tid  = threadIdx.x;
    const int lane = tid & 31;
    const int w    = tid >> 5;
    const int wm   = (w >> 2) * 64;   // warp m offset (2 warps in M)
    const int wn   = (w & 3) * 32;    // warp n offset (4 warps in N)

    const int ldrow = tid >> 1;          // 0..127
    const int ldk   = (tid & 1) * 8;     // 0 or 8

    const float* Aptr = A  + (size_t)(bm + ldrow) * lda + ldk;
    const float* Bptr = Bm + (size_t)(bn + ldrow) * ldb + ldk;

    float acc[4][4][4];
#pragma unroll
    for (int i = 0; i < 4; i++)
#pragma unroll
        for (int j = 0; j < 4; j++)
#pragma unroll
            for (int r = 0; r < 4; r++) acc[i][j][r] = 0.f;

    float4 la0, la1, lb0, lb1;
    auto gload = [&](int k0) {
        la0 = *(const float4*)(Aptr + k0);
        la1 = *(const float4*)(Aptr + k0 + 4);
        lb0 = *(const float4*)(Bptr + k0);
        lb1 = *(const float4*)(Bptr + k0 + 4);
    };

    auto stage = [&](int buf) {
        const int m  = ldrow;
        const int mt = m >> 4;
        const int nt = m >> 3;
        const int l0 = (m & 7) * 4;
        const int regA = (m >> 3) & 1;
        // A, k-quad at ldk (ks = ldk>>3, chi = 0) and ldk+4 (chi = 1)
        {
            int ks = ldk >> 3;
            unsigned* dA = &As[buf][(mt * 2 + ks) * 128];
            int r0 = regA;          // (k&7)<4
            int r1 = regA + 2;      // (k&7)>=4
            dA[(l0 + 0) * 4 + r0] = f2tf32(la0.x);
            dA[(l0 + 1) * 4 + r0] = f2tf32(la0.y);
            dA[(l0 + 2) * 4 + r0] = f2tf32(la0.z);
            dA[(l0 + 3) * 4 + r0] = f2tf32(la0.w);
            dA[(l0 + 0) * 4 + r1] = f2tf32(la1.x);
            dA[(l0 + 1) * 4 + r1] = f2tf32(la1.y);
            dA[(l0 + 2) * 4 + r1] = f2tf32(la1.z);
            dA[(l0 + 3) * 4 + r1] = f2tf32(la1.w);
            unsigned* dB = &Bs[buf][(nt * 2 + ks) * 64];
            dB[(l0 + 0) * 2 + 0] = f2tf32(lb0.x);
            dB[(l0 + 1) * 2 + 0] = f2tf32(lb0.y);
            dB[(l0 + 2) * 2 + 0] = f2tf32(lb0.z);
            dB[(l0 + 3) * 2 + 0] = f2tf32(lb0.w);
            dB[(l0 + 0) * 2 + 1] = f2tf32(lb1.x);
            dB[(l0 + 1) * 2 + 1] = f2tf32(lb1.y);
            dB[(l0 + 2) * 2 + 1] = f2tf32(lb1.z);
            dB[(l0 + 3) * 2 + 1] = f2tf32(lb1.w);
        }
    };

    auto compute = [&](int buf) {
#pragma unroll
        for (int ks = 0; ks < 2; ks++) {
            unsigned a[4][4], b[4][2];
#pragma unroll
            for (int im = 0; im < 4; im++) {
                int mt = (wm >> 4) + im;
                uint4 v = *(const uint4*)&As[buf][((mt * 2 + ks) * 32 + lane) * 4];
                a[im][0] = v.x; a[im][1] = v.y; a[im][2] = v.z; a[im][3] = v.w;
            }
#pragma unroll
            for (int jn = 0; jn < 4; jn++) {
                int nt = (wn >> 3) + jn;
                uint2 v = *(const uint2*)&Bs[buf][((nt * 2 + ks) * 32 + lane) * 2];
                b[jn][0] = v.x; b[jn][1] = v.y;
            }
#pragma unroll
            for (int im = 0; im < 4; im++)
#pragma unroll
                for (int jn = 0; jn < 4; jn++)
                    mma_tf32(acc[im][jn], a[im], b[jn]);
        }
    };

    gload(0);
    stage(0);
    __syncthreads();
    int buf = 0;
    for (int k0 = 16; k0 < K; k0 += 16) {
        gload(k0);
        compute(buf);
        stage(buf ^ 1);
        __syncthreads();
        buf ^= 1;
    }
    compute(buf);

    // epilogue: c0,c1 at (r, 2c),(r,2c+1); c2,c3 at (r+8, ...)
#pragma unroll
    for (int im = 0; im < 4; im++) {
#pragma unroll
        for (int jn = 0; jn < 4; jn++) {
            int m0 = bm + wm + im * 16 + (lane >> 2);
            int n0 = bn + wn + jn * 8 + (lane & 3) * 2;
#pragma unroll
            for (int half = 0; half < 2; half++) {
                int m = m0 + half * 8;
                float v0 = acc[im][jn][half * 2 + 0];
                float v1 = acc[im][jn][half * 2 + 1];
                if (epi == 1) {
                    v0 += bias[n0];     v1 += bias[n0 + 1];
                    v0 = (v0 > 20.f) ? v0 : log1pf(__expf(v0));
                    v1 = (v1 > 20.f) ? v1 : log1pf(__expf(v1));
                } else if (epi == 2) {
                    v0 = sanit(sanit(v0) + res[(size_t)m * N + n0]);
                    v1 = sanit(sanit(v1) + res[(size_t)m * N + n0 + 1]);
                }
                *(float2*)&C[(size_t)m * N + n0] = make_float2(v0, v1);
            }
        }
    }
}

// ---------------- 64x64 tile split-K GEMM (x_proj, N=96) --------------------
__global__ void gemm64sk_kernel(const float* __restrict__ A, int lda,
                                const float* __restrict__ Bm, int ldb,
                                float* __restrict__ C,
                                int M, int N, int kchunk) {
    __shared__ float As[16][65];
    __shared__ float Bs[16][65];
    int bm = blockIdx.y * 64, bn = blockIdx.x * 64;
    int kb = blockIdx.z * kchunk;
    int tid = threadIdx.x;
    int lk = tid & 15, lr = tid >> 4;
    int trow = (tid >> 4) << 2;
    int tcol = (tid & 15) << 2;
    float acc[4][4] = {};

    for (int k0 = kb; k0 < kb + kchunk; k0 += 16) {
#pragma unroll
        for (int i = 0; i < 4; i++) {
            int m = bm + lr + i * 16;
            As[lk][lr + i * 16] = A[(size_t)m * lda + k0 + lk];
            int n = bn + lr + i * 16;
            Bs[lk][lr + i * 16] = (n < N) ? Bm[(size_t)n * ldb + k0 + lk] : 0.f;
        }
        __syncthreads();
#pragma unroll
        for (int kk = 0; kk < 16; kk++) {
            float a[4], bb[4];
#pragma unroll
            for (int i = 0; i < 4; i++) a[i]  = As[kk][trow + i];
#pragma unroll
            for (int j = 0; j < 4; j++) bb[j] = Bs[kk][tcol + j];
#pragma unroll
            for (int i = 0; i < 4; i++)
#pragma unroll
                for (int j = 0; j < 4; j++)
                    acc[i][j] = fmaf(a[i], bb[j], acc[i][j]);
        }
        __syncthreads();
    }
#pragma unroll
    for (int i = 0; i < 4; i++) {
        int m = bm + trow + i;
#pragma unroll
        for (int j = 0; j < 4; j++) {
            int n = bn + tcol + j;
            if (n < N)
                atomicAdd(&C[(size_t)m * N + n], acc[i][j]);
        }
    }
}

// ---------------- causal depthwise conv (k=4) + SiLU -----------------------
__global__ void conv_silu_kernel(const float* __restrict__ cw,
                                 const float* __restrict__ cb) {
    int idx = blockIdx.x * blockDim.x + threadIdx.x;
    if (idx >= BL * DI) return;
    int d   = idx & (DI - 1);
    int row = idx >> 11;
    int l   = row & (L_ - 1);
    float acc = cb[d];
#pragma unroll
    for (int k = 0; k < 4; k++) {
        int ll = l - 3 + k;
        if (ll >= 0)
            acc = fmaf(g_xz[(size_t)(row - 3 + k) * (2 * DI) + d], cw[d * 4 + k], acc);
    }
    acc = acc / (1.f + __expf(-acc));
    g_u[idx] = acc;
}

// ---------------- selective scan + D-skip + gate ----------------------------
__global__ void scan_kernel(const float* __restrict__ A_log,
                            const float* __restrict__ D_skip) {
    int gt = blockIdx.x * blockDim.x + threadIdx.x;
    int n  = gt & 15;
    int d  = (gt >> 4) & (DI - 1);
    int b  = gt >> 15;

    float Aneg = -__expf(A_log[d * DS + n]);
    float Dv   = D_skip[d];
    float h    = 0.f;
    bool head  = (n == 0);

    const float* xd = g_xdbl + (size_t)b * L_ * 96;
    size_t rowbase = (size_t)b * L_;

    for (int t = 0; t < L_; t++) {
        size_t row = rowbase + t;
        float dt = g_delta[row * DI + d];
        float ut = g_u    [row * DI + d];
        float Bt = xd[t * 96 + 64 + n];
        float Ct = xd[t * 96 + 80 + n];

        float dA = __expf(dt * Aneg);
        h = fmaf(dA, h, (dt * ut) * Bt);

        float p = h * Ct;
        p += __shfl_xor_sync(0xffffffffu, p, 1);
        p += __shfl_xor_sync(0xffffffffu, p, 2);
        p += __shfl_xor_sync(0xffffffffu, p, 4);
        p += __shfl_xor_sync(0xffffffffu, p, 8);

        if (head) {
            float z  = g_xz[row * (2 * DI) + DI + d];
            float sz = z / (1.f + __expf(-z));
            g_y[row * DI + d] = (p + ut * Dv) * sz;
        }
    }
}

// ---------------- launch -----------------------------------------------------
extern "C" void kernel_launch(void* const* d_in, const int* in_sizes, int n_in,
                              void* d_out, int out_size) {
    const float* x         = (const float*)d_in[0];
    const float* ln_g      = (const float*)d_in[1];
    const float* ln_b      = (const float*)d_in[2];
    const float* in_proj_w = (const float*)d_in[3];
    const float* conv_w    = (const float*)d_in[4];
    const float* conv_b    = (const float*)d_in[5];
    const float* x_proj_w  = (const float*)d_in[6];
    const float* dt_proj_w = (const float*)d_in[7];
    const float* dt_proj_b = (const float*)d_in[8];
    const float* A_log     = (const float*)d_in[9];
    const float* D_skip    = (const float*)d_in[10];
    const float* out_proj_w= (const float*)d_in[11];
    float* out = (float*)d_out;

    float *p_xn, *p_xz, *p_u, *p_xdbl, *p_delta, *p_y, *p_res;
    cudaGetSymbolAddress((void**)&p_xn,    g_xn);
    cudaGetSymbolAddress((void**)&p_xz,    g_xz);
    cudaGetSymbolAddress((void**)&p_u,     g_u);
    cudaGetSymbolAddress((void**)&p_xdbl,  g_xdbl);
    cudaGetSymbolAddress((void**)&p_delta, g_delta);
    cudaGetSymbolAddress((void**)&p_y,     g_y);
    cudaGetSymbolAddress((void**)&p_res,   g_res);

    // 1. layernorm (+ residual stash)
    ln_kernel<<<BL, 256>>>(x, ln_g, ln_b);

    // 2. in_proj: [4096,1024] x [4096,1024]^T -> [4096,4096]  (tf32 TC)
    gemm_tc_kernel<<<dim3(32, 32), 256>>>(p_xn, DM, in_proj_w, DM, p_xz,
                                          BL, 2 * DI, DM, 0, nullptr, nullptr);

    // 3. depthwise causal conv + silu -> u
    conv_silu_kernel<<<(BL * DI) / 256, 256>>>(conv_w, conv_b);

    // 4. x_proj: [4096,2048] x [96,2048]^T -> [4096,96]  (split-K x8, atomic)
    cudaMemsetAsync(p_xdbl, 0, (size_t)BL * 96 * sizeof(float));
    gemm64sk_kernel<<<dim3(2, 64, 8), 256>>>(p_u, DI, x_proj_w, DI, p_xdbl,
                                             BL, 96, DI / 8);

    // 5. dt_proj + softplus (tf32 TC): [4096,64(ld96)] x [2048,64]^T
    gemm_tc_kernel<<<dim3(16, 32), 256>>>(p_xdbl, 96, dt_proj_w, DTR, p_delta,
                                          BL, DI, DTR, 1, dt_proj_b, nullptr);

    // 6. selective scan + D-skip + silu(z) gate -> y
    scan_kernel<<<256, 256>>>(A_log, D_skip);

    // 7. out_proj + residual + sanitize (tf32 TC) -> out
    gemm_tc_kernel<<<dim3(8, 32), 256>>>(p_y, DI, out_proj_w, DI, out,
                                         BL, DM, DI, 2, nullptr, p_res);
}

// round 6
// speedup vs baseline: 1.6775x; 1.1492x over previous
#include <cuda_runtime.h>
#include <math.h>
#include <stdint.h>

#define B_   2
#define L_   2048
#define DM   1024
#define DI   2048
#define DS   16
#define DTR  64
#define BL   (B_*L_)   /* 4096 rows */

#define STG  3      /* cp.async pipeline stages */
#define CK   32     /* K floats per chunk */

// ---------------- scratch ----------------------------------------------------
__device__ float g_res  [(size_t)BL*DM];
__device__ float g_xn   [(size_t)BL*DM];
__device__ float g_xz   [(size_t)BL*2*DI];
__device__ float g_u    [(size_t)BL*DI];
__device__ float g_xdbl [(size_t)BL*96];
__device__ float g_delta[(size_t)BL*DI];
__device__ float g_y    [(size_t)BL*DI];

__device__ __forceinline__ float sanit(float v) {
    if (isnan(v)) return 0.f;
    if (isinf(v)) return v > 0.f ? 1e4f : -1e4f;
    return v;
}

__device__ __forceinline__ uint32_t smem_u32(const void* p) {
    uint32_t a;
    asm("{ .reg .u64 t; cvta.to.shared.u64 t, %1; cvt.u32.u64 %0, t; }"
        : "=r"(a) : "l"(p));
    return a;
}

__device__ __forceinline__ void cpa16(uint32_t dst, const void* src) {
    asm volatile("cp.async.cg.shared.global [%0], [%1], 16;\n"
                 :: "r"(dst), "l"(src) : "memory");
}

__device__ __forceinline__ void mma_tf32(float* d, const unsigned* a, const unsigned* b) {
    asm volatile(
        "mma.sync.aligned.m16n8k8.row.col.f32.tf32.tf32.f32 "
        "{%0,%1,%2,%3}, {%4,%5,%6,%7}, {%8,%9}, {%0,%1,%2,%3};"
        : "+f"(d[0]), "+f"(d[1]), "+f"(d[2]), "+f"(d[3])
        : "r"(a[0]), "r"(a[1]), "r"(a[2]), "r"(a[3]), "r"(b[0]), "r"(b[1]));
}

// ---------------- LayerNorm --------------------------------------------------
__global__ void ln_kernel(const float* __restrict__ x,
                          const float* __restrict__ g,
                          const float* __restrict__ b) {
    int row = blockIdx.x;
    int tid = threadIdx.x;
    const float* xr = x + (size_t)row * DM;
    float v[4];
    float s = 0.f, s2 = 0.f;
#pragma unroll
    for (int i = 0; i < 4; i++) {
        float t = sanit(xr[tid + i * 256]);
        v[i] = t; s += t; s2 += t * t;
    }
#pragma unroll
    for (int o = 16; o; o >>= 1) {
        s  += __shfl_xor_sync(0xffffffffu, s,  o);
        s2 += __shfl_xor_sync(0xffffffffu, s2, o);
    }
    __shared__ float ss[8], ss2[8], smu, srs;
    int w = tid >> 5, ln = tid & 31;
    if (ln == 0) { ss[w] = s; ss2[w] = s2; }
    __syncthreads();
    if (tid == 0) {
        float a = 0.f, a2 = 0.f;
#pragma unroll
        for (int i = 0; i < 8; i++) { a += ss[i]; a2 += ss2[i]; }
        float mu = a / DM;
        float var = fmaxf(a2 / DM - mu * mu, 0.f);
        smu = mu;
        srs = rsqrtf(var + 1e-5f);
    }
    __syncthreads();
    float mu = smu, rs = srs;
#pragma unroll
    for (int i = 0; i < 4; i++) {
        int c = tid + i * 256;
        g_res[(size_t)row * DM + c] = v[i];
        g_xn [(size_t)row * DM + c] = (v[i] - mu) * rs * g[c] + b[c];
    }
}

// ---------------- HMMA tf32 GEMM: C[M,N] = A[M,K] * B[N,K]^T -----------------
// Block tile 128x128, 8 warps (2x4), warp tile 64x32. K chunk = 32 floats.
// A lda / B ldb row-major K-contiguous, 16B-aligned rows. K % 32 == 0.
// M = grid.y*128 (all rows valid). N may be < grid.x*128 (clamped loads,
// masked stores; N % 8 == 0).
// epi: 0 plain, 1 bias+softplus, 2 sanitize+residual.
__global__ void __launch_bounds__(256, 2)
gemm_hmma(const float* __restrict__ A, int lda,
          const float* __restrict__ Bw, int ldb,
          float* __restrict__ C, int N, int K, int epi,
          const float* __restrict__ bias, const float* __restrict__ res) {
    extern __shared__ float sm[];                 // [STG][8192]
    const int tid  = threadIdx.x;
    const int lane = tid & 31;
    const int w    = tid >> 5;
    const int wm   = (w >> 2) * 64;               // warp M offset
    const int wn   = (w & 3) * 32;                // warp N offset
    const int bm   = blockIdx.y * 128;
    const int bn   = blockIdx.x * 128;
    const int NC   = K / CK;

    const uint32_t smb = smem_u32(sm);

    float acc[4][4][4];
#pragma unroll
    for (int i = 0; i < 4; i++)
#pragma unroll
        for (int j = 0; j < 4; j++)
#pragma unroll
            for (int r = 0; r < 4; r++) acc[i][j][r] = 0.f;

    // per-thread fill coordinates: 4 segments of 16B for A, 4 for B
    auto fill = [&](int c) {
        if (c < NC) {
            const int slot = c % STG;
            const int k0   = c * CK;
            const uint32_t abase = smb + (uint32_t)slot * 32768u;
            const uint32_t bbase = abase + 16384u;
#pragma unroll
            for (int i = 0; i < 4; i++) {
                int q   = tid + i * 256;           // 0..1023
                int row = q >> 3, s = q & 7;
                uint32_t dw = ((uint32_t)row * 32u +
                               ((uint32_t)(s ^ (row & 7)) << 2)) << 2;  // bytes
                cpa16(abase + dw, A + (size_t)(bm + row) * lda + k0 + s * 4);
                int br = bn + row; if (br > N - 1) br = N - 1;
                cpa16(bbase + dw, Bw + (size_t)br * ldb + k0 + s * 4);
            }
        }
        asm volatile("cp.async.commit_group;" ::: "memory");
    };

    fill(0);
    fill(1);

    const int t  = lane & 3;
    const int r8 = lane >> 2;                     // 0..7
    for (int c = 0; c < NC; c++) {
        asm volatile("cp.async.wait_group 1;" ::: "memory");
        __syncthreads();
        fill(c + 2);

        const int slot = c % STG;
        const unsigned* As = (const unsigned*)(sm + (size_t)slot * 8192);
        const unsigned* Bs = As + 4096;
#pragma unroll
        for (int ks = 0; ks < 4; ks++) {
            const int g0 = (2 * ks)     ^ r8;     // A row&7 == r8, B col&7 == r8
            const int g1 = (2 * ks + 1) ^ r8;
            unsigned af[4][4], bf[4][2];
#pragma unroll
            for (int im = 0; im < 4; im++) {
                int r0 = (wm + im * 16 + r8) * 32;
                af[im][0] = As[r0 +       g0 * 4 + t];
                af[im][1] = As[r0 + 256 + g0 * 4 + t];   // +8 rows
                af[im][2] = As[r0 +       g1 * 4 + t];
                af[im][3] = As[r0 + 256 + g1 * 4 + t];
            }
#pragma unroll
            for (int jn = 0; jn < 4; jn++) {
                int c0 = (wn + jn * 8 + r8) * 32;
                bf[jn][0] = Bs[c0 + g0 * 4 + t];
                bf[jn][1] = Bs[c0 + g1 * 4 + t];
            }
#pragma unroll
            for (int im = 0; im < 4; im++)
#pragma unroll
                for (int jn = 0; jn < 4; jn++)
                    mma_tf32(acc[im][jn], af[im], bf[jn]);
        }
        __syncthreads();
    }

    // epilogue: c0,c1 -> (row, 2c),(row, 2c+1); c2,c3 -> (row+8, ...)
#pragma unroll
    for (int im = 0; im < 4; im++) {
#pragma unroll
        for (int jn = 0; jn < 4; jn++) {
            int m0 = bm + wm + im * 16 + r8;
            int n0 = bn + wn + jn * 8 + t * 2;
            if (n0 >= N) continue;
#pragma unroll
            for (int half = 0; half < 2; half++) {
                int m = m0 + half * 8;
                float v0 = acc[im][jn][half * 2 + 0];
                float v1 = acc[im][jn][half * 2 + 1];
                if (epi == 1) {
                    v0 += bias[n0];     v1 += bias[n0 + 1];
                    v0 = (v0 > 20.f) ? v0 : log1pf(__expf(v0));
                    v1 = (v1 > 20.f) ? v1 : log1pf(__expf(v1));
                } else if (epi == 2) {
                    v0 = sanit(sanit(v0) + res[(size_t)m * N + n0]);
                    v1 = sanit(sanit(v1) + res[(size_t)m * N + n0 + 1]);
                }
                *(float2*)&C[(size_t)m * N + n0] = make_float2(v0, v1);
            }
        }
    }
}

// ---------------- causal depthwise conv (k=4) + SiLU -----------------------
__global__ void conv_silu_kernel(const float* __restrict__ cw,
                                 const float* __restrict__ cb) {
    int idx = blockIdx.x * blockDim.x + threadIdx.x;
    if (idx >= BL * DI) return;
    int d   = idx & (DI - 1);
    int row = idx >> 11;
    int l   = row & (L_ - 1);
    float acc = cb[d];
#pragma unroll
    for (int k = 0; k < 4; k++) {
        int ll = l - 3 + k;
        if (ll >= 0)
            acc = fmaf(g_xz[(size_t)(row - 3 + k) * (2 * DI) + d], cw[d * 4 + k], acc);
    }
    acc = acc / (1.f + __expf(-acc));
    g_u[idx] = acc;
}

// ---------------- selective scan + D-skip + gate ----------------------------
__global__ void scan_kernel(const float* __restrict__ A_log,
                            const float* __restrict__ D_skip) {
    int gt = blockIdx.x * blockDim.x + threadIdx.x;
    int n  = gt & 15;
    int d  = (gt >> 4) & (DI - 1);
    int b  = gt >> 15;

    float Aneg = -__expf(A_log[d * DS + n]);
    float Dv   = D_skip[d];
    float h    = 0.f;
    bool head  = (n == 0);

    const float* xd = g_xdbl + (size_t)b * L_ * 96;
    size_t rowbase = (size_t)b * L_;

    for (int t = 0; t < L_; t++) {
        size_t row = rowbase + t;
        float dt = g_delta[row * DI + d];
        float ut = g_u    [row * DI + d];
        float Bt = xd[t * 96 + 64 + n];
        float Ct = xd[t * 96 + 80 + n];

        float dA = __expf(dt * Aneg);
        h = fmaf(dA, h, (dt * ut) * Bt);

        float p = h * Ct;
        p += __shfl_xor_sync(0xffffffffu, p, 1);
        p += __shfl_xor_sync(0xffffffffu, p, 2);
        p += __shfl_xor_sync(0xffffffffu, p, 4);
        p += __shfl_xor_sync(0xffffffffu, p, 8);

        if (head) {
            float z  = g_xz[row * (2 * DI) + DI + d];
            float sz = z / (1.f + __expf(-z));
            g_y[row * DI + d] = (p + ut * Dv) * sz;
        }
    }
}

// ---------------- launch -----------------------------------------------------
extern "C" void kernel_launch(void* const* d_in, const int* in_sizes, int n_in,
                              void* d_out, int out_size) {
    const float* x         = (const float*)d_in[0];
    const float* ln_g      = (const float*)d_in[1];
    const float* ln_b      = (const float*)d_in[2];
    const float* in_proj_w = (const float*)d_in[3];
    const float* conv_w    = (const float*)d_in[4];
    const float* conv_b    = (const float*)d_in[5];
    const float* x_proj_w  = (const float*)d_in[6];
    const float* dt_proj_w = (const float*)d_in[7];
    const float* dt_proj_b = (const float*)d_in[8];
    const float* A_log     = (const float*)d_in[9];
    const float* D_skip    = (const float*)d_in[10];
    const float* out_proj_w= (const float*)d_in[11];
    float* out = (float*)d_out;

    float *p_xn, *p_xz, *p_u, *p_xdbl, *p_delta, *p_y, *p_res;
    cudaGetSymbolAddress((void**)&p_xn,    g_xn);
    cudaGetSymbolAddress((void**)&p_xz,    g_xz);
    cudaGetSymbolAddress((void**)&p_u,     g_u);
    cudaGetSymbolAddress((void**)&p_xdbl,  g_xdbl);
    cudaGetSymbolAddress((void**)&p_delta, g_delta);
    cudaGetSymbolAddress((void**)&p_y,     g_y);
    cudaGetSymbolAddress((void**)&p_res,   g_res);

    const int SMEM_GB = STG * 32768;   // 96 KB
    cudaFuncSetAttribute(gemm_hmma, cudaFuncAttributeMaxDynamicSharedMemorySize,
                         SMEM_GB);

    // 1. layernorm (+ residual stash)
    ln_kernel<<<BL, 256>>>(x, ln_g, ln_b);

    // 2. in_proj: [4096,1024] x [4096,1024]^T -> [4096,4096]
    gemm_hmma<<<dim3(32, 32), 256, SMEM_GB>>>(p_xn, DM, in_proj_w, DM, p_xz,
                                              2 * DI, DM, 0, nullptr, nullptr);

    // 3. depthwise causal conv + silu -> u
    conv_silu_kernel<<<(BL * DI) / 256, 256>>>(conv_w, conv_b);

    // 4. x_proj: [4096,2048] x [96,2048]^T -> [4096,96]
    gemm_hmma<<<dim3(1, 32), 256, SMEM_GB>>>(p_u, DI, x_proj_w, DI, p_xdbl,
                                             96, DI, 0, nullptr, nullptr);

    // 5. dt_proj + softplus: [4096,64(ld96)] x [2048,64]^T -> delta
    gemm_hmma<<<dim3(16, 32), 256, SMEM_GB>>>(p_xdbl, 96, dt_proj_w, DTR, p_delta,
                                              DI, DTR, 1, dt_proj_b, nullptr);

    // 6. selective scan + D-skip + silu(z) gate -> y
    scan_kernel<<<256, 256>>>(A_log, D_skip);

    // 7. out_proj + residual + sanitize -> out
    gemm_hmma<<<dim3(8, 32), 256, SMEM_GB>>>(p_y, DI, out_proj_w, DI, out,
                                             DM, DI, 2, nullptr, p_res);
}

// round 7
// speedup vs baseline: 5.0755x; 3.0257x over previous
#include <cuda_runtime.h>
#include <math.h>
#include <stdint.h>

#define B_   2
#define L_   2048
#define DM   1024
#define DI   2048
#define DS   16
#define DTR  64
#define BL   (B_*L_)   /* 4096 rows */

#define STG  3      /* cp.async pipeline stages (gemm) */
#define CK   32     /* K floats per chunk (gemm) */
#define TT   64     /* timesteps per scan tile */

// ---------------- scratch ----------------------------------------------------
__device__ float g_res  [(size_t)BL*DM];
__device__ float g_xn   [(size_t)BL*DM];
__device__ float g_xz   [(size_t)BL*2*DI];
__device__ float g_u    [(size_t)BL*DI];
__device__ float g_xdbl [(size_t)BL*96];
__device__ float g_delta[(size_t)BL*DI];
__device__ float g_y    [(size_t)BL*DI];

__device__ __forceinline__ float sanit(float v) {
    if (isnan(v)) return 0.f;
    if (isinf(v)) return v > 0.f ? 1e4f : -1e4f;
    return v;
}

__device__ __forceinline__ uint32_t smem_u32(const void* p) {
    uint32_t a;
    asm("{ .reg .u64 t; cvta.to.shared.u64 t, %1; cvt.u32.u64 %0, t; }"
        : "=r"(a) : "l"(p));
    return a;
}

__device__ __forceinline__ void cpa16(uint32_t dst, const void* src) {
    asm volatile("cp.async.cg.shared.global [%0], [%1], 16;\n"
                 :: "r"(dst), "l"(src) : "memory");
}

__device__ __forceinline__ void mma_tf32(float* d, const unsigned* a, const unsigned* b) {
    asm volatile(
        "mma.sync.aligned.m16n8k8.row.col.f32.tf32.tf32.f32 "
        "{%0,%1,%2,%3}, {%4,%5,%6,%7}, {%8,%9}, {%0,%1,%2,%3};"
        : "+f"(d[0]), "+f"(d[1]), "+f"(d[2]), "+f"(d[3])
        : "r"(a[0]), "r"(a[1]), "r"(a[2]), "r"(a[3]), "r"(b[0]), "r"(b[1]));
}

// ---------------- LayerNorm --------------------------------------------------
__global__ void ln_kernel(const float* __restrict__ x,
                          const float* __restrict__ g,
                          const float* __restrict__ b) {
    int row = blockIdx.x;
    int tid = threadIdx.x;
    const float* xr = x + (size_t)row * DM;
    float v[4];
    float s = 0.f, s2 = 0.f;
#pragma unroll
    for (int i = 0; i < 4; i++) {
        float t = sanit(xr[tid + i * 256]);
        v[i] = t; s += t; s2 += t * t;
    }
#pragma unroll
    for (int o = 16; o; o >>= 1) {
        s  += __shfl_xor_sync(0xffffffffu, s,  o);
        s2 += __shfl_xor_sync(0xffffffffu, s2, o);
    }
    __shared__ float ss[8], ss2[8], smu, srs;
    int w = tid >> 5, ln = tid & 31;
    if (ln == 0) { ss[w] = s; ss2[w] = s2; }
    __syncthreads();
    if (tid == 0) {
        float a = 0.f, a2 = 0.f;
#pragma unroll
        for (int i = 0; i < 8; i++) { a += ss[i]; a2 += ss2[i]; }
        float mu = a / DM;
        float var = fmaxf(a2 / DM - mu * mu, 0.f);
        smu = mu;
        srs = rsqrtf(var + 1e-5f);
    }
    __syncthreads();
    float mu = smu, rs = srs;
#pragma unroll
    for (int i = 0; i < 4; i++) {
        int c = tid + i * 256;
        g_res[(size_t)row * DM + c] = v[i];
        g_xn [(size_t)row * DM + c] = (v[i] - mu) * rs * g[c] + b[c];
    }
}

// ---------------- HMMA tf32 GEMM: C[M,N] = A[M,K] * B[N,K]^T -----------------
// Block tile 128x128, 8 warps (2x4), warp tile 64x32. K chunk = 32 floats.
// K here is PER-SPLIT K (multiple of 32); blockIdx.z selects the K-slice.
// epi: 0 plain, 1 bias+softplus, 2 sanitize+residual, 3 atomicAdd (split-K).
__global__ void __launch_bounds__(256, 2)
gemm_hmma(const float* __restrict__ A, int lda,
          const float* __restrict__ Bw, int ldb,
          float* __restrict__ C, int N, int K, int epi,
          const float* __restrict__ bias, const float* __restrict__ res) {
    extern __shared__ float sm[];                 // [STG][8192]
    const int tid  = threadIdx.x;
    const int lane = tid & 31;
    const int w    = tid >> 5;
    const int wm   = (w >> 2) * 64;               // warp M offset
    const int wn   = (w & 3) * 32;                // warp N offset
    const int bm   = blockIdx.y * 128;
    const int bn   = blockIdx.x * 128;
    const int NC   = K / CK;

    A  += (size_t)blockIdx.z * K;                 // split-K slice
    Bw += (size_t)blockIdx.z * K;

    const uint32_t smb = smem_u32(sm);

    float acc[4][4][4];
#pragma unroll
    for (int i = 0; i < 4; i++)
#pragma unroll
        for (int j = 0; j < 4; j++)
#pragma unroll
            for (int r = 0; r < 4; r++) acc[i][j][r] = 0.f;

    auto fill = [&](int c) {
        if (c < NC) {
            const int slot = c % STG;
            const int k0   = c * CK;
            const uint32_t abase = smb + (uint32_t)slot * 32768u;
            const uint32_t bbase = abase + 16384u;
#pragma unroll
            for (int i = 0; i < 4; i++) {
                int q   = tid + i * 256;           // 0..1023
                int row = q >> 3, s = q & 7;
                uint32_t dw = ((uint32_t)row * 32u +
                               ((uint32_t)(s ^ (row & 7)) << 2)) << 2;  // bytes
                cpa16(abase + dw, A + (size_t)(bm + row) * lda + k0 + s * 4);
                int br = bn + row; if (br > N - 1) br = N - 1;
                cpa16(bbase + dw, Bw + (size_t)br * ldb + k0 + s * 4);
            }
        }
        asm volatile("cp.async.commit_group;" ::: "memory");
    };

    fill(0);
    fill(1);

    const int t  = lane & 3;
    const int r8 = lane >> 2;                     // 0..7
    for (int c = 0; c < NC; c++) {
        asm volatile("cp.async.wait_group 1;" ::: "memory");
        __syncthreads();
        fill(c + 2);

        const int slot = c % STG;
        const unsigned* As = (const unsigned*)(sm + (size_t)slot * 8192);
        const unsigned* Bs = As + 4096;
#pragma unroll
        for (int ks = 0; ks < 4; ks++) {
            const int g0 = (2 * ks)     ^ r8;
            const int g1 = (2 * ks + 1) ^ r8;
            unsigned af[4][4], bf[4][2];
#pragma unroll
            for (int im = 0; im < 4; im++) {
                int r0 = (wm + im * 16 + r8) * 32;
                af[im][0] = As[r0 +       g0 * 4 + t];
                af[im][1] = As[r0 + 256 + g0 * 4 + t];
                af[im][2] = As[r0 +       g1 * 4 + t];
                af[im][3] = As[r0 + 256 + g1 * 4 + t];
            }
#pragma unroll
            for (int jn = 0; jn < 4; jn++) {
                int c0 = (wn + jn * 8 + r8) * 32;
                bf[jn][0] = Bs[c0 + g0 * 4 + t];
                bf[jn][1] = Bs[c0 + g1 * 4 + t];
            }
#pragma unroll
            for (int im = 0; im < 4; im++)
#pragma unroll
                for (int jn = 0; jn < 4; jn++)
                    mma_tf32(acc[im][jn], af[im], bf[jn]);
        }
        __syncthreads();
    }

#pragma unroll
    for (int im = 0; im < 4; im++) {
#pragma unroll
        for (int jn = 0; jn < 4; jn++) {
            int m0 = bm + wm + im * 16 + r8;
            int n0 = bn + wn + jn * 8 + t * 2;
            if (n0 >= N) continue;
#pragma unroll
            for (int half = 0; half < 2; half++) {
                int m = m0 + half * 8;
                float v0 = acc[im][jn][half * 2 + 0];
                float v1 = acc[im][jn][half * 2 + 1];
                if (epi == 1) {
                    v0 += bias[n0];     v1 += bias[n0 + 1];
                    v0 = (v0 > 20.f) ? v0 : log1pf(__expf(v0));
                    v1 = (v1 > 20.f) ? v1 : log1pf(__expf(v1));
                } else if (epi == 2) {
                    v0 = sanit(sanit(v0) + res[(size_t)m * N + n0]);
                    v1 = sanit(sanit(v1) + res[(size_t)m * N + n0 + 1]);
                } else if (epi == 3) {
                    atomicAdd(&C[(size_t)m * N + n0],     v0);
                    atomicAdd(&C[(size_t)m * N + n0 + 1], v1);
                    continue;
                }
                *(float2*)&C[(size_t)m * N + n0] = make_float2(v0, v1);
            }
        }
    }
}

// ---------------- causal depthwise conv (k=4) + SiLU -----------------------
__global__ void conv_silu_kernel(const float* __restrict__ cw,
                                 const float* __restrict__ cb) {
    int idx = blockIdx.x * blockDim.x + threadIdx.x;
    if (idx >= BL * DI) return;
    int d   = idx & (DI - 1);
    int row = idx >> 11;
    int l   = row & (L_ - 1);
    float acc = cb[d];
#pragma unroll
    for (int k = 0; k < 4; k++) {
        int ll = l - 3 + k;
        if (ll >= 0)
            acc = fmaf(g_xz[(size_t)(row - 3 + k) * (2 * DI) + d], cw[d * 4 + k], acc);
    }
    acc = acc / (1.f + __expf(-acc));
    g_u[idx] = acc;
}

// ---------------- selective scan (smem-staged) + D-skip + gate ---------------
// block = 512 threads = 32 channels (dl) x 16 states (n); grid = (DI/32, B_).
// Inputs staged per 64-t tile via double-buffered cp.async; y written coalesced.
__global__ void __launch_bounds__(512)
scan2_kernel(const float* __restrict__ A_log, const float* __restrict__ D_skip) {
    extern __shared__ float s[];
    // layout (floats): sd[2][64][32] @0, su @4096, sz @8192,
    //                  sB[2][64][16] @12288, sC @14336, sy[64][32] @16384
    float* sd = s;
    float* su = s + 4096;
    float* sz = s + 8192;
    float* sB = s + 12288;
    float* sC = s + 14336;
    float* sy = s + 16384;

    const int tid = threadIdx.x;
    const int n   = tid & 15;
    const int dl  = tid >> 4;            // 0..31
    const int d0  = blockIdx.x * 32;
    const int b   = blockIdx.y;
    const int d   = d0 + dl;

    const float Aneg = -__expf(A_log[d * DS + n]);
    const float Dv   = D_skip[d];
    float h = 0.f;
    const size_t rb = (size_t)b * L_;

    const int prow = tid >> 3, pseg = (tid & 7) * 4;   // 64 x 8 segments
    auto prefetch = [&](int tile, int buf) {
        size_t r = rb + (size_t)tile * TT + prow;
        cpa16(smem_u32(&sd[buf * 2048 + prow * 32 + pseg]),
              g_delta + r * DI + d0 + pseg);
        cpa16(smem_u32(&su[buf * 2048 + prow * 32 + pseg]),
              g_u + r * DI + d0 + pseg);
        cpa16(smem_u32(&sz[buf * 2048 + prow * 32 + pseg]),
              g_xz + r * (2 * DI) + DI + d0 + pseg);
        if (tid < 256) {
            int rw = tid >> 2, sg = (tid & 3) * 4;
            cpa16(smem_u32(&sB[buf * 1024 + rw * 16 + sg]),
                  g_xdbl + (rb + (size_t)tile * TT + rw) * 96 + 64 + sg);
        } else {
            int q = tid - 256;
            int rw = q >> 2, sg = (q & 3) * 4;
            cpa16(smem_u32(&sC[buf * 1024 + rw * 16 + sg]),
                  g_xdbl + (rb + (size_t)tile * TT + rw) * 96 + 80 + sg);
        }
        asm volatile("cp.async.commit_group;" ::: "memory");
    };

    prefetch(0, 0);
    const int NT = L_ / TT;
    for (int tile = 0; tile < NT; tile++) {
        const int buf = tile & 1;
        if (tile + 1 < NT) {
            prefetch(tile + 1, buf ^ 1);
            asm volatile("cp.async.wait_group 1;" ::: "memory");
        } else {
            asm volatile("cp.async.wait_group 0;" ::: "memory");
        }
        __syncthreads();

        const float* pd = sd + buf * 2048;
        const float* pu = su + buf * 2048;
        const float* pz = sz + buf * 2048;
        const float* pB = sB + buf * 1024;
        const float* pC = sC + buf * 1024;
#pragma unroll 4
        for (int t = 0; t < TT; t++) {
            float dt = pd[t * 32 + dl];
            float ut = pu[t * 32 + dl];
            float Bt = pB[t * 16 + n];
            float Ct = pC[t * 16 + n];
            float dA = __expf(dt * Aneg);
            h = fmaf(dA, h, (dt * ut) * Bt);
            float p = h * Ct;
            p += __shfl_xor_sync(0xffffffffu, p, 1);
            p += __shfl_xor_sync(0xffffffffu, p, 2);
            p += __shfl_xor_sync(0xffffffffu, p, 4);
            p += __shfl_xor_sync(0xffffffffu, p, 8);
            if (n == 0) {
                float z  = pz[t * 32 + dl];
                float sg = z / (1.f + __expf(-z));
                sy[t * 32 + dl] = (p + ut * Dv) * sg;
            }
        }
        __syncthreads();

        // coalesced write-out of the tile's y
        float4 v = *(const float4*)&sy[prow * 32 + pseg];
        *(float4*)&g_y[(rb + (size_t)tile * TT + prow) * DI + d0 + pseg] = v;
    }
}

// ---------------- launch -----------------------------------------------------
extern "C" void kernel_launch(void* const* d_in, const int* in_sizes, int n_in,
                              void* d_out, int out_size) {
    const float* x         = (const float*)d_in[0];
    const float* ln_g      = (const float*)d_in[1];
    const float* ln_b      = (const float*)d_in[2];
    const float* in_proj_w = (const float*)d_in[3];
    const float* conv_w    = (const float*)d_in[4];
    const float* conv_b    = (const float*)d_in[5];
    const float* x_proj_w  = (const float*)d_in[6];
    const float* dt_proj_w = (const float*)d_in[7];
    const float* dt_proj_b = (const float*)d_in[8];
    const float* A_log     = (const float*)d_in[9];
    const float* D_skip    = (const float*)d_in[10];
    const float* out_proj_w= (const float*)d_in[11];
    float* out = (float*)d_out;

    float *p_xn, *p_xz, *p_u, *p_xdbl, *p_delta, *p_y, *p_res;
    cudaGetSymbolAddress((void**)&p_xn,    g_xn);
    cudaGetSymbolAddress((void**)&p_xz,    g_xz);
    cudaGetSymbolAddress((void**)&p_u,     g_u);
    cudaGetSymbolAddress((void**)&p_xdbl,  g_xdbl);
    cudaGetSymbolAddress((void**)&p_delta, g_delta);
    cudaGetSymbolAddress((void**)&p_y,     g_y);
    cudaGetSymbolAddress((void**)&p_res,   g_res);

    const int SMEM_GB = STG * 32768;        // 96 KB
    const int SMEM_SC = 18432 * 4;          // 72 KB
    cudaFuncSetAttribute(gemm_hmma, cudaFuncAttributeMaxDynamicSharedMemorySize,
                         SMEM_GB);
    cudaFuncSetAttribute(scan2_kernel, cudaFuncAttributeMaxDynamicSharedMemorySize,
                         SMEM_SC);

    // 1. layernorm (+ residual stash)
    ln_kernel<<<BL, 256>>>(x, ln_g, ln_b);

    // 2. in_proj: [4096,1024] x [4096,1024]^T -> [4096,4096]
    gemm_hmma<<<dim3(32, 32), 256, SMEM_GB>>>(p_xn, DM, in_proj_w, DM, p_xz,
                                              2 * DI, DM, 0, nullptr, nullptr);

    // 3. depthwise causal conv + silu -> u
    conv_silu_kernel<<<(BL * DI) / 256, 256>>>(conv_w, conv_b);

    // 4. x_proj: [4096,2048] x [96,2048]^T -> [4096,96]   (split-K x4)
    cudaMemsetAsync(p_xdbl, 0, (size_t)BL * 96 * sizeof(float));
    gemm_hmma<<<dim3(1, 32, 4), 256, SMEM_GB>>>(p_u, DI, x_proj_w, DI, p_xdbl,
                                                96, DI / 4, 3, nullptr, nullptr);

    // 5. dt_proj + softplus: [4096,64(ld96)] x [2048,64]^T -> delta
    gemm_hmma<<<dim3(16, 32), 256, SMEM_GB>>>(p_xdbl, 96, dt_proj_w, DTR, p_delta,
                                              DI, DTR, 1, dt_proj_b, nullptr);

    // 6. selective scan + D-skip + silu(z) gate -> y
    scan2_kernel<<<dim3(DI / 32, B_), 512, SMEM_SC>>>(A_log, D_skip);

    // 7. out_proj + residual + sanitize -> out
    gemm_hmma<<<dim3(8, 32), 256, SMEM_GB>>>(p_y, DI, out_proj_w, DI, out,
                                             DM, DI, 2, nullptr, p_res);
}

// round 8
// speedup vs baseline: 6.1936x; 1.2203x over previous
#include <cuda_runtime.h>
#include <cuda_fp16.h>
#include <math.h>
#include <stdint.h>

#define B_   2
#define L_   2048
#define DM   1024
#define DI   2048
#define DS   16
#define DTR  64
#define BL   (B_*L_)   /* 4096 rows */

#define STG  3      /* cp.async pipeline stages (gemm) */
#define CK   64     /* K halves per chunk (gemm) = 128B row */
#define TT   64     /* timesteps per scan tile */

// ---------------- scratch ----------------------------------------------------
__device__ float  g_res  [(size_t)BL*DM];
__device__ float  g_xz   [(size_t)BL*2*DI];
__device__ float  g_u    [(size_t)BL*DI];
__device__ float  g_xdbl [(size_t)BL*96];
__device__ float  g_delta[(size_t)BL*DI];

__device__ __half g_xn_h [(size_t)BL*DM];
__device__ __half g_u_h  [(size_t)BL*DI];
__device__ __half g_y_h  [(size_t)BL*DI];
__device__ __half g_dt_h [(size_t)BL*DTR];
__device__ __half h_inw  [(size_t)2*DI*DM];
__device__ __half h_xpw  [(size_t)96*DI];
__device__ __half h_dtw  [(size_t)DI*DTR];
__device__ __half h_opw  [(size_t)DM*DI];

__device__ __forceinline__ float sanit(float v) {
    if (isnan(v)) return 0.f;
    if (isinf(v)) return v > 0.f ? 1e4f : -1e4f;
    return v;
}

__device__ __forceinline__ uint32_t smem_u32(const void* p) {
    uint32_t a;
    asm("{ .reg .u64 t; cvta.to.shared.u64 t, %1; cvt.u32.u64 %0, t; }"
        : "=r"(a) : "l"(p));
    return a;
}

__device__ __forceinline__ void cpa16(uint32_t dst, const void* src) {
    asm volatile("cp.async.cg.shared.global [%0], [%1], 16;\n"
                 :: "r"(dst), "l"(src) : "memory");
}

__device__ __forceinline__ void ldm_x4(unsigned* r, uint32_t addr) {
    asm volatile("ldmatrix.sync.aligned.m8n8.x4.shared.b16 {%0,%1,%2,%3}, [%4];"
                 : "=r"(r[0]), "=r"(r[1]), "=r"(r[2]), "=r"(r[3]) : "r"(addr));
}

__device__ __forceinline__ void mma_f16(float* d, const unsigned* a,
                                        unsigned b0, unsigned b1) {
    asm volatile(
        "mma.sync.aligned.m16n8k16.row.col.f32.f16.f16.f32 "
        "{%0,%1,%2,%3}, {%4,%5,%6,%7}, {%8,%9}, {%0,%1,%2,%3};"
        : "+f"(d[0]), "+f"(d[1]), "+f"(d[2]), "+f"(d[3])
        : "r"(a[0]), "r"(a[1]), "r"(a[2]), "r"(a[3]), "r"(b0), "r"(b1));
}

// ---------------- fp32 -> fp16 convert ---------------------------------------
__global__ void f2h_kernel(const float* __restrict__ src, __half* __restrict__ dst,
                           int n) {
    int i = blockIdx.x * blockDim.x + threadIdx.x;
    if (i < n) dst[i] = __float2half_rn(src[i]);
}

// x_proj dt rows (96-stride fp32) -> packed 64-wide half
__global__ void dt2h_kernel() {
    int i = blockIdx.x * blockDim.x + threadIdx.x;   // over BL*64
    if (i >= BL * DTR) return;
    int r = i >> 6, c = i & 63;
    g_dt_h[i] = __float2half_rn(g_xdbl[(size_t)r * 96 + c]);
}

// ---------------- LayerNorm --------------------------------------------------
__global__ void ln_kernel(const float* __restrict__ x,
                          const float* __restrict__ g,
                          const float* __restrict__ b) {
    int row = blockIdx.x;
    int tid = threadIdx.x;
    const float* xr = x + (size_t)row * DM;
    float v[4];
    float s = 0.f, s2 = 0.f;
#pragma unroll
    for (int i = 0; i < 4; i++) {
        float t = sanit(xr[tid + i * 256]);
        v[i] = t; s += t; s2 += t * t;
    }
#pragma unroll
    for (int o = 16; o; o >>= 1) {
        s  += __shfl_xor_sync(0xffffffffu, s,  o);
        s2 += __shfl_xor_sync(0xffffffffu, s2, o);
    }
    __shared__ float ss[8], ss2[8], smu, srs;
    int w = tid >> 5, ln = tid & 31;
    if (ln == 0) { ss[w] = s; ss2[w] = s2; }
    __syncthreads();
    if (tid == 0) {
        float a = 0.f, a2 = 0.f;
#pragma unroll
        for (int i = 0; i < 8; i++) { a += ss[i]; a2 += ss2[i]; }
        float mu = a / DM;
        float var = fmaxf(a2 / DM - mu * mu, 0.f);
        smu = mu;
        srs = rsqrtf(var + 1e-5f);
    }
    __syncthreads();
    float mu = smu, rs = srs;
#pragma unroll
    for (int i = 0; i < 4; i++) {
        int c = tid + i * 256;
        g_res[(size_t)row * DM + c] = v[i];
        g_xn_h[(size_t)row * DM + c] =
            __float2half_rn((v[i] - mu) * rs * g[c] + b[c]);
    }
}

// ---------------- fp16 HMMA GEMM: C[M,N] = A[M,K] * B[N,K]^T -----------------
// Block 128x128, 8 warps (2x4), warp 64x32, K chunk = 64 halves (128B rows,
// SW128 swizzle, ldmatrix fragment loads). K (per split) % 64 == 0.
// epi: 0 plain f32 store, 1 bias+softplus, 2 sanitize+residual, 3 atomicAdd.
__global__ void __launch_bounds__(256, 2)
gemm_hf(const __half* __restrict__ A, int lda,
        const __half* __restrict__ Bw, int ldb,
        float* __restrict__ C, int N, int K, int epi,
        const float* __restrict__ bias, const float* __restrict__ res) {
    extern __shared__ __half sm[];                // [STG][128*64 A + 128*64 B]
    const int tid  = threadIdx.x;
    const int lane = tid & 31;
    const int w    = tid >> 5;
    const int wm   = (w >> 2) * 64;
    const int wn   = (w & 3) * 32;
    const int bm   = blockIdx.y * 128;
    const int bn   = blockIdx.x * 128;
    const int NC   = K / CK;

    A  += (size_t)blockIdx.z * K;
    Bw += (size_t)blockIdx.z * K;

    const uint32_t smb = smem_u32(sm);

    float acc[4][4][4];
#pragma unroll
    for (int i = 0; i < 4; i++)
#pragma unroll
        for (int j = 0; j < 4; j++)
#pragma unroll
            for (int r = 0; r < 4; r++) acc[i][j][r] = 0.f;

    const int frow = tid >> 3, fseg = tid & 7;    // fill coords: 4 iters x 32 rows
    auto fill = [&](int c) {
        if (c < NC) {
            const int slot = c % STG;
            const int k0   = c * CK;
            const uint32_t abase = smb + (uint32_t)slot * 32768u;
            const uint32_t bbase = abase + 16384u;
#pragma unroll
            for (int i = 0; i < 4; i++) {
                int row = frow + i * 32;
                uint32_t dw = (uint32_t)row * 128u +
                              (((uint32_t)fseg * 16u) ^ (((uint32_t)row & 7u) << 4));
                cpa16(abase + dw, A + (size_t)(bm + row) * lda + k0 + fseg * 8);
                int br = bn + row; if (br > N - 1) br = N - 1;
                cpa16(bbase + dw, Bw + (size_t)br * ldb + k0 + fseg * 8);
            }
        }
        asm volatile("cp.async.commit_group;" ::: "memory");
    };

    fill(0);
    fill(1);

    // ldmatrix per-lane address pre-computation
    const int rowin = lane & 7;
    const int gb0   = (lane >> 3) & 1;
    const int gb1   = lane >> 4;
    uint32_t abaseA[4], xrA[4];
#pragma unroll
    for (int im = 0; im < 4; im++) {
        int rowA = wm + im * 16 + gb0 * 8 + rowin;
        abaseA[im] = (uint32_t)rowA * 128u;
        xrA[im]    = ((uint32_t)rowA & 7u) << 4;
    }
    uint32_t abaseB[2], xrB[2];
#pragma unroll
    for (int jp = 0; jp < 2; jp++) {
        int rowB = wn + jp * 16 + gb1 * 8 + rowin;
        abaseB[jp] = (uint32_t)rowB * 128u;
        xrB[jp]    = ((uint32_t)rowB & 7u) << 4;
    }
    const uint32_t kA_off = (uint32_t)gb1 * 16u;   // within kstep
    const uint32_t kB_off = (uint32_t)gb0 * 16u;

    for (int c = 0; c < NC; c++) {
        asm volatile("cp.async.wait_group 1;" ::: "memory");
        __syncthreads();
        fill(c + 2);

        const int slot = c % STG;
        const uint32_t ab = smb + (uint32_t)slot * 32768u;
        const uint32_t bb = ab + 16384u;
#pragma unroll
        for (int ks = 0; ks < 4; ks++) {
            const uint32_t kbA = (uint32_t)ks * 32u + kA_off;
            const uint32_t kbB = (uint32_t)ks * 32u + kB_off;
            unsigned a[4][4], bp[2][4];
#pragma unroll
            for (int im = 0; im < 4; im++)
                ldm_x4(a[im], ab + abaseA[im] + (kbA ^ xrA[im]));
#pragma unroll
            for (int jp = 0; jp < 2; jp++)
                ldm_x4(bp[jp], bb + abaseB[jp] + (kbB ^ xrB[jp]));
#pragma unroll
            for (int im = 0; im < 4; im++) {
#pragma unroll
                for (int jp = 0; jp < 2; jp++) {
                    mma_f16(acc[im][2 * jp],     a[im], bp[jp][0], bp[jp][1]);
                    mma_f16(acc[im][2 * jp + 1], a[im], bp[jp][2], bp[jp][3]);
                }
            }
        }
    }

    const int t  = lane & 3;
    const int r8 = lane >> 2;
#pragma unroll
    for (int im = 0; im < 4; im++) {
#pragma unroll
        for (int jn = 0; jn < 4; jn++) {
            int m0 = bm + wm + im * 16 + r8;
            int n0 = bn + wn + jn * 8 + t * 2;
            if (n0 >= N) continue;
#pragma unroll
            for (int half = 0; half < 2; half++) {
                int m = m0 + half * 8;
                float v0 = acc[im][jn][half * 2 + 0];
                float v1 = acc[im][jn][half * 2 + 1];
                if (epi == 1) {
                    v0 += bias[n0];     v1 += bias[n0 + 1];
                    v0 = (v0 > 20.f) ? v0 : log1pf(__expf(v0));
                    v1 = (v1 > 20.f) ? v1 : log1pf(__expf(v1));
                } else if (epi == 2) {
                    v0 = sanit(sanit(v0) + res[(size_t)m * N + n0]);
                    v1 = sanit(sanit(v1) + res[(size_t)m * N + n0 + 1]);
                } else if (epi == 3) {
                    atomicAdd(&C[(size_t)m * N + n0],     v0);
                    atomicAdd(&C[(size_t)m * N + n0 + 1], v1);
                    continue;
                }
                *(float2*)&C[(size_t)m * N + n0] = make_float2(v0, v1);
            }
        }
    }
}

// ---------------- causal depthwise conv (k=4) + SiLU -----------------------
__global__ void conv_silu_kernel(const float* __restrict__ cw,
                                 const float* __restrict__ cb) {
    int idx = blockIdx.x * blockDim.x + threadIdx.x;
    if (idx >= BL * DI) return;
    int d   = idx & (DI - 1);
    int row = idx >> 11;
    int l   = row & (L_ - 1);
    float acc = cb[d];
#pragma unroll
    for (int k = 0; k < 4; k++) {
        int ll = l - 3 + k;
        if (ll >= 0)
            acc = fmaf(g_xz[(size_t)(row - 3 + k) * (2 * DI) + d], cw[d * 4 + k], acc);
    }
    acc = acc / (1.f + __expf(-acc));
    g_u[idx]   = acc;
    g_u_h[idx] = __float2half_rn(acc);
}

// ---------------- selective scan (smem-staged) + D-skip + gate ---------------
__global__ void __launch_bounds__(512)
scan2_kernel(const float* __restrict__ A_log, const float* __restrict__ D_skip) {
    extern __shared__ float s[];
    float* sd = s;
    float* su = s + 4096;
    float* sz = s + 8192;
    float* sB = s + 12288;
    float* sC = s + 14336;
    float* sy = s + 16384;

    const int tid = threadIdx.x;
    const int n   = tid & 15;
    const int dl  = tid >> 4;
    const int d0  = blockIdx.x * 32;
    const int b   = blockIdx.y;
    const int d   = d0 + dl;

    const float Aneg = -__expf(A_log[d * DS + n]);
    const float Dv   = D_skip[d];
    float h = 0.f;
    const size_t rb = (size_t)b * L_;

    const int prow = tid >> 3, pseg = (tid & 7) * 4;
    auto prefetch = [&](int tile, int buf) {
        size_t r = rb + (size_t)tile * TT + prow;
        cpa16(smem_u32(&sd[buf * 2048 + prow * 32 + pseg]),
              g_delta + r * DI + d0 + pseg);
        cpa16(smem_u32(&su[buf * 2048 + prow * 32 + pseg]),
              g_u + r * DI + d0 + pseg);
        cpa16(smem_u32(&sz[buf * 2048 + prow * 32 + pseg]),
              g_xz + r * (2 * DI) + DI + d0 + pseg);
        if (tid < 256) {
            int rw = tid >> 2, sg = (tid & 3) * 4;
            cpa16(smem_u32(&sB[buf * 1024 + rw * 16 + sg]),
                  g_xdbl + (rb + (size_t)tile * TT + rw) * 96 + 64 + sg);
        } else {
            int q = tid - 256;
            int rw = q >> 2, sg = (q & 3) * 4;
            cpa16(smem_u32(&sC[buf * 1024 + rw * 16 + sg]),
                  g_xdbl + (rb + (size_t)tile * TT + rw) * 96 + 80 + sg);
        }
        asm volatile("cp.async.commit_group;" ::: "memory");
    };

    prefetch(0, 0);
    const int NT = L_ / TT;
    for (int tile = 0; tile < NT; tile++) {
        const int buf = tile & 1;
        if (tile + 1 < NT) {
            prefetch(tile + 1, buf ^ 1);
            asm volatile("cp.async.wait_group 1;" ::: "memory");
        } else {
            asm volatile("cp.async.wait_group 0;" ::: "memory");
        }
        __syncthreads();

        const float* pd = sd + buf * 2048;
        const float* pu = su + buf * 2048;
        const float* pz = sz + buf * 2048;
        const float* pB = sB + buf * 1024;
        const float* pC = sC + buf * 1024;
#pragma unroll 4
        for (int t = 0; t < TT; t++) {
            float dt = pd[t * 32 + dl];
            float ut = pu[t * 32 + dl];
            float Bt = pB[t * 16 + n];
            float Ct = pC[t * 16 + n];
            float dA = __expf(dt * Aneg);
            h = fmaf(dA, h, (dt * ut) * Bt);
            float p = h * Ct;
            p += __shfl_xor_sync(0xffffffffu, p, 1);
            p += __shfl_xor_sync(0xffffffffu, p, 2);
            p += __shfl_xor_sync(0xffffffffu, p, 4);
            p += __shfl_xor_sync(0xffffffffu, p, 8);
            if (n == 0) {
                float z  = pz[t * 32 + dl];
                float sg = z / (1.f + __expf(-z));
                sy[t * 32 + dl] = (p + ut * Dv) * sg;
            }
        }
        __syncthreads();

        float4 v = *(const float4*)&sy[prow * 32 + pseg];
        __half2 h01 = __floats2half2_rn(v.x, v.y);
        __half2 h23 = __floats2half2_rn(v.z, v.w);
        __half2* dst = (__half2*)&g_y_h[(rb + (size_t)tile * TT + prow) * DI + d0 + pseg];
        dst[0] = h01;
        dst[1] = h23;
    }
}

// ---------------- launch -----------------------------------------------------
extern "C" void kernel_launch(void* const* d_in, const int* in_sizes, int n_in,
                              void* d_out, int out_size) {
    const float* x         = (const float*)d_in[0];
    const float* ln_g      = (const float*)d_in[1];
    const float* ln_b      = (const float*)d_in[2];
    const float* in_proj_w = (const float*)d_in[3];
    const float* conv_w    = (const float*)d_in[4];
    const float* conv_b    = (const float*)d_in[5];
    const float* x_proj_w  = (const float*)d_in[6];
    const float* dt_proj_w = (const float*)d_in[7];
    const float* dt_proj_b = (const float*)d_in[8];
    const float* A_log     = (const float*)d_in[9];
    const float* D_skip    = (const float*)d_in[10];
    const float* out_proj_w= (const float*)d_in[11];
    float* out = (float*)d_out;

    float *p_xz, *p_u, *p_xdbl, *p_delta, *p_res;
    __half *p_xnh, *p_uh, *p_yh, *p_dth, *p_inw, *p_xpw, *p_dtw, *p_opw;
    cudaGetSymbolAddress((void**)&p_xz,    g_xz);
    cudaGetSymbolAddress((void**)&p_u,     g_u);
    cudaGetSymbolAddress((void**)&p_xdbl,  g_xdbl);
    cudaGetSymbolAddress((void**)&p_delta, g_delta);
    cudaGetSymbolAddress((void**)&p_res,   g_res);
    cudaGetSymbolAddress((void**)&p_xnh,   g_xn_h);
    cudaGetSymbolAddress((void**)&p_uh,    g_u_h);
    cudaGetSymbolAddress((void**)&p_yh,    g_y_h);
    cudaGetSymbolAddress((void**)&p_dth,   g_dt_h);
    cudaGetSymbolAddress((void**)&p_inw,   h_inw);
    cudaGetSymbolAddress((void**)&p_xpw,   h_xpw);
    cudaGetSymbolAddress((void**)&p_dtw,   h_dtw);
    cudaGetSymbolAddress((void**)&p_opw,   h_opw);

    const int SMEM_GB = STG * 32768;        // 96 KB
    const int SMEM_SC = 18432 * 4;          // 72 KB
    cudaFuncSetAttribute(gemm_hf, cudaFuncAttributeMaxDynamicSharedMemorySize,
                         SMEM_GB);
    cudaFuncSetAttribute(scan2_kernel, cudaFuncAttributeMaxDynamicSharedMemorySize,
                         SMEM_SC);

    // 0. weight conversion fp32 -> fp16
    f2h_kernel<<<(2 * DI * DM) / 256, 256>>>(in_proj_w, p_inw, 2 * DI * DM);
    f2h_kernel<<<(96 * DI) / 256, 256>>>(x_proj_w, p_xpw, 96 * DI);
    f2h_kernel<<<(DI * DTR) / 256, 256>>>(dt_proj_w, p_dtw, DI * DTR);
    f2h_kernel<<<(DM * DI) / 256, 256>>>(out_proj_w, p_opw, DM * DI);

    // 1. layernorm (+ residual stash, fp16 xn)
    ln_kernel<<<BL, 256>>>(x, ln_g, ln_b);

    // 2. in_proj: [4096,1024] x [4096,1024]^T -> [4096,4096]
    gemm_hf<<<dim3(32, 32), 256, SMEM_GB>>>(p_xnh, DM, p_inw, DM, p_xz,
                                            2 * DI, DM, 0, nullptr, nullptr);

    // 3. depthwise causal conv + silu -> u (fp32 + fp16)
    conv_silu_kernel<<<(BL * DI) / 256, 256>>>(conv_w, conv_b);

    // 4. x_proj: [4096,2048] x [96,2048]^T -> [4096,96]   (split-K x4)
    cudaMemsetAsync(p_xdbl, 0, (size_t)BL * 96 * sizeof(float));
    gemm_hf<<<dim3(1, 32, 4), 256, SMEM_GB>>>(p_uh, DI, p_xpw, DI, p_xdbl,
                                              96, DI / 4, 3, nullptr, nullptr);
    dt2h_kernel<<<(BL * DTR) / 256, 256>>>();

    // 5. dt_proj + softplus: [4096,64] x [2048,64]^T -> delta
    gemm_hf<<<dim3(16, 32), 256, SMEM_GB>>>(p_dth, DTR, p_dtw, DTR, p_delta,
                                            DI, DTR, 1, dt_proj_b, nullptr);

    // 6. selective scan + D-skip + silu(z) gate -> y (fp16)
    scan2_kernel<<<dim3(DI / 32, B_), 512, SMEM_SC>>>(A_log, D_skip);

    // 7. out_proj + residual + sanitize -> out
    gemm_hf<<<dim3(8, 32), 256, SMEM_GB>>>(p_yh, DI, p_opw, DI, out,
                                           DM, DI, 2, nullptr, p_res);
}

// round 9
// speedup vs baseline: 6.6539x; 1.0743x over previous
#include <cuda_runtime.h>
#include <cuda_fp16.h>
#include <math.h>
#include <stdint.h>

#define B_   2
#define L_   2048
#define DM   1024
#define DI   2048
#define DS   16
#define DTR  64
#define BL   (B_*L_)   /* 4096 rows */

#define STG  3      /* cp.async pipeline stages (gemm) */
#define CK   64     /* K halves per chunk (gemm) = 128B row */
#define TT   64     /* timesteps per scan tile */

// ---------------- scratch ----------------------------------------------------
__device__ float  g_xdbl [(size_t)BL*96];
__device__ float  g_delta[(size_t)BL*DI];

__device__ __half g_xn_h [(size_t)BL*DM];
__device__ __half g_xz_h [(size_t)BL*2*DI];
__device__ __half g_u_h  [(size_t)BL*DI];
__device__ __half g_y_h  [(size_t)BL*DI];
__device__ __half g_dt_h [(size_t)BL*DTR];
__device__ __half h_inw  [(size_t)2*DI*DM];
__device__ __half h_xpw  [(size_t)96*DI];
__device__ __half h_dtw  [(size_t)DI*DTR];
__device__ __half h_opw  [(size_t)DM*DI];

__device__ __forceinline__ float sanit(float v) {
    if (isnan(v)) return 0.f;
    if (isinf(v)) return v > 0.f ? 1e4f : -1e4f;
    return v;
}

__device__ __forceinline__ uint32_t smem_u32(const void* p) {
    uint32_t a;
    asm("{ .reg .u64 t; cvta.to.shared.u64 t, %1; cvt.u32.u64 %0, t; }"
        : "=r"(a) : "l"(p));
    return a;
}

__device__ __forceinline__ void cpa16(uint32_t dst, const void* src) {
    asm volatile("cp.async.cg.shared.global [%0], [%1], 16;\n"
                 :: "r"(dst), "l"(src) : "memory");
}

__device__ __forceinline__ void ldm_x4(unsigned* r, uint32_t addr) {
    asm volatile("ldmatrix.sync.aligned.m8n8.x4.shared.b16 {%0,%1,%2,%3}, [%4];"
                 : "=r"(r[0]), "=r"(r[1]), "=r"(r[2]), "=r"(r[3]) : "r"(addr));
}

__device__ __forceinline__ void mma_f16(float* d, const unsigned* a,
                                        unsigned b0, unsigned b1) {
    asm volatile(
        "mma.sync.aligned.m16n8k16.row.col.f32.f16.f16.f32 "
        "{%0,%1,%2,%3}, {%4,%5,%6,%7}, {%8,%9}, {%0,%1,%2,%3};"
        : "+f"(d[0]), "+f"(d[1]), "+f"(d[2]), "+f"(d[3])
        : "r"(a[0]), "r"(a[1]), "r"(a[2]), "r"(a[3]), "r"(b0), "r"(b1));
}

// ---------------- all-weights fp32 -> fp16 (one kernel, float4) --------------
#define NQ0 (2*DI*DM/4)
#define NQ1 (96*DI/4)
#define NQ2 (DI*DTR/4)
#define NQ3 (DM*DI/4)
__global__ void wconv_kernel(const float* __restrict__ w0, const float* __restrict__ w1,
                             const float* __restrict__ w2, const float* __restrict__ w3) {
    int i = blockIdx.x * blockDim.x + threadIdx.x;
    const float* s; __half* d; int j = i;
    if (j < NQ0) { s = w0; d = h_inw; }
    else { j -= NQ0;
        if (j < NQ1) { s = w1; d = h_xpw; }
        else { j -= NQ1;
            if (j < NQ2) { s = w2; d = h_dtw; }
            else { j -= NQ2; if (j >= NQ3) return; s = w3; d = h_opw; }
        }
    }
    float4 v = ((const float4*)s)[j];
    __half2 a = __floats2half2_rn(v.x, v.y);
    __half2 b = __floats2half2_rn(v.z, v.w);
    ((__half2*)d)[2 * j]     = a;
    ((__half2*)d)[2 * j + 1] = b;
}

// x_proj dt rows (96-stride fp32) -> packed 64-wide half
__global__ void dt2h_kernel() {
    int i = blockIdx.x * blockDim.x + threadIdx.x;   // quad over BL*64
    if (i >= BL * 16) return;
    int r = i >> 4, c = (i & 15) * 4;
    float4 v = *(const float4*)&g_xdbl[(size_t)r * 96 + c];
    __half2 a = __floats2half2_rn(v.x, v.y);
    __half2 b = __floats2half2_rn(v.z, v.w);
    *(__half2*)&g_dt_h[(size_t)r * 64 + c]     = a;
    *(__half2*)&g_dt_h[(size_t)r * 64 + c + 2] = b;
}

// ---------------- LayerNorm --------------------------------------------------
__global__ void ln_kernel(const float* __restrict__ x,
                          const float* __restrict__ g,
                          const float* __restrict__ b) {
    int row = blockIdx.x;
    int tid = threadIdx.x;
    const float* xr = x + (size_t)row * DM;
    float v[4];
    float s = 0.f, s2 = 0.f;
#pragma unroll
    for (int i = 0; i < 4; i++) {
        float t = sanit(xr[tid + i * 256]);
        v[i] = t; s += t; s2 += t * t;
    }
#pragma unroll
    for (int o = 16; o; o >>= 1) {
        s  += __shfl_xor_sync(0xffffffffu, s,  o);
        s2 += __shfl_xor_sync(0xffffffffu, s2, o);
    }
    __shared__ float ss[8], ss2[8], smu, srs;
    int w = tid >> 5, ln = tid & 31;
    if (ln == 0) { ss[w] = s; ss2[w] = s2; }
    __syncthreads();
    if (tid == 0) {
        float a = 0.f, a2 = 0.f;
#pragma unroll
        for (int i = 0; i < 8; i++) { a += ss[i]; a2 += ss2[i]; }
        float mu = a / DM;
        float var = fmaxf(a2 / DM - mu * mu, 0.f);
        smu = mu;
        srs = rsqrtf(var + 1e-5f);
    }
    __syncthreads();
    float mu = smu, rs = srs;
#pragma unroll
    for (int i = 0; i < 4; i++) {
        int c = tid + i * 256;
        g_xn_h[(size_t)row * DM + c] =
            __float2half_rn((v[i] - mu) * rs * g[c] + b[c]);
    }
}

// ---------------- fp16 HMMA GEMM: C[M,N] = A[M,K] * B[N,K]^T -----------------
// Block 128x128, 8 warps (2x4), warp 64x32, K chunk = 64 halves.
// epi: 0 f32 store, 1 bias+softplus f32, 2 sanitize+residual f32,
//      3 atomicAdd f32 (split-K), 4 plain fp16 store.
__global__ void __launch_bounds__(256, 2)
gemm_hf(const __half* __restrict__ A, int lda,
        const __half* __restrict__ Bw, int ldb,
        void* __restrict__ Cv, int N, int K, int epi,
        const float* __restrict__ bias, const float* __restrict__ res) {
    extern __shared__ __half sm[];
    const int tid  = threadIdx.x;
    const int lane = tid & 31;
    const int w    = tid >> 5;
    const int wm   = (w >> 2) * 64;
    const int wn   = (w & 3) * 32;
    const int bm   = blockIdx.y * 128;
    const int bn   = blockIdx.x * 128;
    const int NC   = K / CK;

    A  += (size_t)blockIdx.z * K;
    Bw += (size_t)blockIdx.z * K;

    const uint32_t smb = smem_u32(sm);

    float acc[4][4][4];
#pragma unroll
    for (int i = 0; i < 4; i++)
#pragma unroll
        for (int j = 0; j < 4; j++)
#pragma unroll
            for (int r = 0; r < 4; r++) acc[i][j][r] = 0.f;

    const int frow = tid >> 3, fseg = tid & 7;
    auto fill = [&](int c) {
        if (c < NC) {
            const int slot = c % STG;
            const int k0   = c * CK;
            const uint32_t abase = smb + (uint32_t)slot * 32768u;
            const uint32_t bbase = abase + 16384u;
#pragma unroll
            for (int i = 0; i < 4; i++) {
                int row = frow + i * 32;
                uint32_t dw = (uint32_t)row * 128u +
                              (((uint32_t)fseg * 16u) ^ (((uint32_t)row & 7u) << 4));
                cpa16(abase + dw, A + (size_t)(bm + row) * lda + k0 + fseg * 8);
                int br = bn + row; if (br > N - 1) br = N - 1;
                cpa16(bbase + dw, Bw + (size_t)br * ldb + k0 + fseg * 8);
            }
        }
        asm volatile("cp.async.commit_group;" ::: "memory");
    };

    fill(0);
    fill(1);

    const int rowin = lane & 7;
    const int gb0   = (lane >> 3) & 1;
    const int gb1   = lane >> 4;
    uint32_t abaseA[4], xrA[4];
#pragma unroll
    for (int im = 0; im < 4; im++) {
        int rowA = wm + im * 16 + gb0 * 8 + rowin;
        abaseA[im] = (uint32_t)rowA * 128u;
        xrA[im]    = ((uint32_t)rowA & 7u) << 4;
    }
    uint32_t abaseB[2], xrB[2];
#pragma unroll
    for (int jp = 0; jp < 2; jp++) {
        int rowB = wn + jp * 16 + gb1 * 8 + rowin;
        abaseB[jp] = (uint32_t)rowB * 128u;
        xrB[jp]    = ((uint32_t)rowB & 7u) << 4;
    }
    const uint32_t kA_off = (uint32_t)gb1 * 16u;
    const uint32_t kB_off = (uint32_t)gb0 * 16u;

    for (int c = 0; c < NC; c++) {
        asm volatile("cp.async.wait_group 1;" ::: "memory");
        __syncthreads();
        fill(c + 2);

        const int slot = c % STG;
        const uint32_t ab = smb + (uint32_t)slot * 32768u;
        const uint32_t bb = ab + 16384u;
#pragma unroll
        for (int ks = 0; ks < 4; ks++) {
            const uint32_t kbA = (uint32_t)ks * 32u + kA_off;
            const uint32_t kbB = (uint32_t)ks * 32u + kB_off;
            unsigned a[4][4], bp[2][4];
#pragma unroll
            for (int im = 0; im < 4; im++)
                ldm_x4(a[im], ab + abaseA[im] + (kbA ^ xrA[im]));
#pragma unroll
            for (int jp = 0; jp < 2; jp++)
                ldm_x4(bp[jp], bb + abaseB[jp] + (kbB ^ xrB[jp]));
#pragma unroll
            for (int im = 0; im < 4; im++) {
#pragma unroll
                for (int jp = 0; jp < 2; jp++) {
                    mma_f16(acc[im][2 * jp],     a[im], bp[jp][0], bp[jp][1]);
                    mma_f16(acc[im][2 * jp + 1], a[im], bp[jp][2], bp[jp][3]);
                }
            }
        }
    }

    float* Cf = (float*)Cv;
    __half* Ch = (__half*)Cv;
    const int t  = lane & 3;
    const int r8 = lane >> 2;
#pragma unroll
    for (int im = 0; im < 4; im++) {
#pragma unroll
        for (int jn = 0; jn < 4; jn++) {
            int m0 = bm + wm + im * 16 + r8;
            int n0 = bn + wn + jn * 8 + t * 2;
            if (n0 >= N) continue;
#pragma unroll
            for (int half = 0; half < 2; half++) {
                int m = m0 + half * 8;
                float v0 = acc[im][jn][half * 2 + 0];
                float v1 = acc[im][jn][half * 2 + 1];
                if (epi == 4) {
                    *(__half2*)&Ch[(size_t)m * N + n0] = __floats2half2_rn(v0, v1);
                    continue;
                } else if (epi == 1) {
                    v0 += bias[n0];     v1 += bias[n0 + 1];
                    v0 = (v0 > 20.f) ? v0 : log1pf(__expf(v0));
                    v1 = (v1 > 20.f) ? v1 : log1pf(__expf(v1));
                } else if (epi == 2) {
                    v0 = sanit(sanit(v0) + res[(size_t)m * N + n0]);
                    v1 = sanit(sanit(v1) + res[(size_t)m * N + n0 + 1]);
                } else if (epi == 3) {
                    atomicAdd(&Cf[(size_t)m * N + n0],     v0);
                    atomicAdd(&Cf[(size_t)m * N + n0 + 1], v1);
                    continue;
                }
                *(float2*)&Cf[(size_t)m * N + n0] = make_float2(v0, v1);
            }
        }
    }
}

// ---------------- causal depthwise conv (k=4) + SiLU, fp16 in/out ------------
__global__ void conv_silu_kernel(const float* __restrict__ cw,
                                 const float* __restrict__ cb) {
    int i = blockIdx.x * blockDim.x + threadIdx.x;   // over BL*DI/2
    if (i >= BL * DI / 2) return;
    int d2  = i & (DI / 2 - 1);
    int row = i >> 10;
    int l   = row & (L_ - 1);
    int d   = d2 * 2;
    float a0 = cb[d], a1 = cb[d + 1];
#pragma unroll
    for (int k = 0; k < 4; k++) {
        int ll = l - 3 + k;
        if (ll >= 0) {
            __half2 v = *(const __half2*)&g_xz_h[(size_t)(row - 3 + k) * (2 * DI) + d];
            float2 vf = __half22float2(v);
            a0 = fmaf(vf.x, cw[d * 4 + k],       a0);
            a1 = fmaf(vf.y, cw[(d + 1) * 4 + k], a1);
        }
    }
    a0 = a0 / (1.f + __expf(-a0));
    a1 = a1 / (1.f + __expf(-a1));
    *(__half2*)&g_u_h[(size_t)row * DI + d] = __floats2half2_rn(a0, a1);
}

// ---------------- selective scan v3: 2 states/lane ---------------------------
// block = 256 threads = 32 channels x 8 lanes (states 2s,2s+1); grid (64, B_).
__global__ void __launch_bounds__(256)
scan3_kernel(const float* __restrict__ A_log, const float* __restrict__ D_skip) {
    extern __shared__ char smc[];
    float*  sdp = (float*)(smc);              // [2][64][32] f32  (16KB)
    __half* sup = (__half*)(smc + 16384);     // [2][64][32] f16  (8KB)
    __half* szp = (__half*)(smc + 24576);     // [2][64][32] f16  (8KB)
    float*  sBp = (float*)(smc + 32768);      // [2][64][16] f32  (8KB)
    float*  sCp = (float*)(smc + 40960);      // [2][64][16] f32  (8KB)
    float*  syp = (float*)(smc + 49152);      // [64][32]    f32  (8KB)

    const int tid = threadIdx.x;
    const int s   = tid & 7;          // state pair
    const int dl  = tid >> 3;         // 0..31 channel
    const int d0  = blockIdx.x * 32;
    const int b   = blockIdx.y;
    const int d   = d0 + dl;

    const float An0 = -__expf(A_log[d * DS + 2 * s]);
    const float An1 = -__expf(A_log[d * DS + 2 * s + 1]);
    const float dAn = An1 - An0;
    const float Dv  = D_skip[d];
    float h0 = 0.f, h1 = 0.f;
    const size_t rb = (size_t)b * L_;

    const uint32_t a_sd = smem_u32(sdp);
    const uint32_t a_su = smem_u32(sup);
    const uint32_t a_sz = smem_u32(szp);
    const uint32_t a_sB = smem_u32(sBp);
    const uint32_t a_sC = smem_u32(sCp);

    auto prefetch = [&](int tile, int buf) {
        size_t r0 = rb + (size_t)tile * TT;
#pragma unroll
        for (int rep = 0; rep < 2; rep++) {                     // delta f32: 512 segs
            int seg = tid + rep * 256;
            int row = seg >> 3, c4 = (seg & 7) * 4;
            cpa16(a_sd + (uint32_t)(buf * 2048 + row * 32 + c4) * 4,
                  g_delta + (r0 + row) * DI + d0 + c4);
        }
        {                                                        // u f16: 256 segs
            int row = tid >> 2, ch = (tid & 3) * 8;
            cpa16(a_su + (uint32_t)(buf * 2048 + row * 32 + ch) * 2,
                  g_u_h + (r0 + row) * DI + d0 + ch);
        }
        {                                                        // z f16: 256 segs
            int row = tid >> 2, ch = (tid & 3) * 8;
            cpa16(a_sz + (uint32_t)(buf * 2048 + row * 32 + ch) * 2,
                  g_xz_h + (r0 + row) * (2 * DI) + DI + d0 + ch);
        }
        {                                                        // B f32: 256 segs
            int row = tid >> 2, cf = (tid & 3) * 4;
            cpa16(a_sB + (uint32_t)(buf * 1024 + row * 16 + cf) * 4,
                  g_xdbl + (r0 + row) * 96 + 64 + cf);
        }
        {                                                        // C f32: 256 segs
            int row = tid >> 2, cf = (tid & 3) * 4;
            cpa16(a_sC + (uint32_t)(buf * 1024 + row * 16 + cf) * 4,
                  g_xdbl + (r0 + row) * 96 + 80 + cf);
        }
        asm volatile("cp.async.commit_group;" ::: "memory");
    };

    prefetch(0, 0);
    const int NT = L_ / TT;
    for (int tile = 0; tile < NT; tile++) {
        const int buf = tile & 1;
        if (tile + 1 < NT) {
            prefetch(tile + 1, buf ^ 1);
            asm volatile("cp.async.wait_group 1;" ::: "memory");
        } else {
            asm volatile("cp.async.wait_group 0;" ::: "memory");
        }
        __syncthreads();

        const float*  pd = sdp + buf * 2048;
        const __half* pu = sup + buf * 2048;
        const __half* pz = szp + buf * 2048;
        const float*  pB = sBp + buf * 1024;
        const float*  pC = sCp + buf * 1024;
#pragma unroll 4
        for (int t = 0; t < TT; t++) {
            float dt = pd[t * 32 + dl];
            float ut = __half2float(pu[t * 32 + dl]);
            float2 Bt = *(const float2*)&pB[t * 16 + 2 * s];
            float2 Ct = *(const float2*)&pC[t * 16 + 2 * s];
            float e0 = __expf(dt * An0);
            float q  = __expf(dt * dAn);
            float du = dt * ut;
            h0 = fmaf(e0,     h0, du * Bt.x);
            h1 = fmaf(e0 * q, h1, du * Bt.y);
            float p = fmaf(h1, Ct.y, h0 * Ct.x);
            p += __shfl_xor_sync(0xffffffffu, p, 1);
            p += __shfl_xor_sync(0xffffffffu, p, 2);
            p += __shfl_xor_sync(0xffffffffu, p, 4);
            if (s == 0) {
                float z  = __half2float(pz[t * 32 + dl]);
                float sg = z / (1.f + __expf(-z));
                syp[t * 32 + dl] = (p + ut * Dv) * sg;
            }
        }
        __syncthreads();

        // write-out: 8 floats per thread -> 4 half2 (16B store)
        {
            int row = tid >> 2, col = (tid & 3) * 8;
            float4 v0 = *(const float4*)&syp[row * 32 + col];
            float4 v1 = *(const float4*)&syp[row * 32 + col + 4];
            __half2 o0 = __floats2half2_rn(v0.x, v0.y);
            __half2 o1 = __floats2half2_rn(v0.z, v0.w);
            __half2 o2 = __floats2half2_rn(v1.x, v1.y);
            __half2 o3 = __floats2half2_rn(v1.z, v1.w);
            uint4 pk = make_uint4(*(unsigned*)&o0, *(unsigned*)&o1,
                                  *(unsigned*)&o2, *(unsigned*)&o3);
            *(uint4*)&g_y_h[(rb + (size_t)tile * TT + row) * DI + d0 + col] = pk;
        }
    }
}

// ---------------- launch -----------------------------------------------------
extern "C" void kernel_launch(void* const* d_in, const int* in_sizes, int n_in,
                              void* d_out, int out_size) {
    const float* x         = (const float*)d_in[0];
    const float* ln_g      = (const float*)d_in[1];
    const float* ln_b      = (const float*)d_in[2];
    const float* in_proj_w = (const float*)d_in[3];
    const float* conv_w    = (const float*)d_in[4];
    const float* conv_b    = (const float*)d_in[5];
    const float* x_proj_w  = (const float*)d_in[6];
    const float* dt_proj_w = (const float*)d_in[7];
    const float* dt_proj_b = (const float*)d_in[8];
    const float* A_log     = (const float*)d_in[9];
    const float* D_skip    = (const float*)d_in[10];
    const float* out_proj_w= (const float*)d_in[11];
    float* out = (float*)d_out;

    float *p_xdbl, *p_delta;
    __half *p_xnh, *p_xzh, *p_uh, *p_yh, *p_dth, *p_inw, *p_xpw, *p_dtw, *p_opw;
    cudaGetSymbolAddress((void**)&p_xdbl,  g_xdbl);
    cudaGetSymbolAddress((void**)&p_delta, g_delta);
    cudaGetSymbolAddress((void**)&p_xnh,   g_xn_h);
    cudaGetSymbolAddress((void**)&p_xzh,   g_xz_h);
    cudaGetSymbolAddress((void**)&p_uh,    g_u_h);
    cudaGetSymbolAddress((void**)&p_yh,    g_y_h);
    cudaGetSymbolAddress((void**)&p_dth,   g_dt_h);
    cudaGetSymbolAddress((void**)&p_inw,   h_inw);
    cudaGetSymbolAddress((void**)&p_xpw,   h_xpw);
    cudaGetSymbolAddress((void**)&p_dtw,   h_dtw);
    cudaGetSymbolAddress((void**)&p_opw,   h_opw);

    const int SMEM_GB = STG * 32768;        // 96 KB
    const int SMEM_SC = 57344;              // 56 KB
    cudaFuncSetAttribute(gemm_hf, cudaFuncAttributeMaxDynamicSharedMemorySize,
                         SMEM_GB);
    cudaFuncSetAttribute(scan3_kernel, cudaFuncAttributeMaxDynamicSharedMemorySize,
                         SMEM_SC);

    // 0. all weights fp32 -> fp16 (single kernel)
    const int NQ = NQ0 + NQ1 + NQ2 + NQ3;
    wconv_kernel<<<(NQ + 255) / 256, 256>>>(in_proj_w, x_proj_w, dt_proj_w,
                                            out_proj_w);

    // 1. layernorm -> fp16 xn
    ln_kernel<<<BL, 256>>>(x, ln_g, ln_b);

    // 2. in_proj -> fp16 xz
    gemm_hf<<<dim3(32, 32), 256, SMEM_GB>>>(p_xnh, DM, p_inw, DM, p_xzh,
                                            2 * DI, DM, 4, nullptr, nullptr);

    // 3. depthwise causal conv + silu -> fp16 u
    conv_silu_kernel<<<(BL * DI / 2) / 256, 256>>>(conv_w, conv_b);

    // 4. x_proj (split-K x4, atomic fp32)
    cudaMemsetAsync(p_xdbl, 0, (size_t)BL * 96 * sizeof(float));
    gemm_hf<<<dim3(1, 32, 4), 256, SMEM_GB>>>(p_uh, DI, p_xpw, DI, p_xdbl,
                                              96, DI / 4, 3, nullptr, nullptr);
    dt2h_kernel<<<(BL * 16) / 256, 256>>>();

    // 5. dt_proj + softplus -> fp32 delta
    gemm_hf<<<dim3(16, 32), 256, SMEM_GB>>>(p_dth, DTR, p_dtw, DTR, p_delta,
                                            DI, DTR, 1, dt_proj_b, nullptr);

    // 6. selective scan + D-skip + silu(z) gate -> fp16 y
    scan3_kernel<<<dim3(DI / 32, B_), 256, SMEM_SC>>>(A_log, D_skip);

    // 7. out_proj + residual(x) + sanitize -> out
    gemm_hf<<<dim3(8, 32), 256, SMEM_GB>>>(p_yh, DI, p_opw, DI, out,
                                           DM, DI, 2, nullptr, x);
}

// round 10
// speedup vs baseline: 6.9370x; 1.0425x over previous
#include <cuda_runtime.h>
#include <cuda_fp16.h>
#include <math.h>
#include <stdint.h>

#define B_   2
#define L_   2048
#define DM   1024
#define DI   2048
#define DS   16
#define DTR  64
#define BL   (B_*L_)   /* 4096 rows */

#define STG  3      /* cp.async pipeline stages (gemm) */
#define CK   64     /* K halves per chunk (gemm) = 128B row */
#define TT   64     /* timesteps per scan tile */
#define CT   64     /* timesteps per conv tile */

// ---------------- scratch ----------------------------------------------------
__device__ float  g_xdbl [(size_t)BL*96];
__device__ float  g_delta[(size_t)BL*DI];

__device__ __half g_xn_h [(size_t)BL*DM];
__device__ __half g_xz_h [(size_t)BL*2*DI];
__device__ __half g_u_h  [(size_t)BL*DI];
__device__ __half g_y_h  [(size_t)BL*DI];
__device__ __half g_dt_h [(size_t)BL*DTR];
__device__ __half h_inw  [(size_t)2*DI*DM];
__device__ __half h_xpw  [(size_t)96*DI];
__device__ __half h_dtw  [(size_t)DI*DTR];
__device__ __half h_opw  [(size_t)DM*DI];

__device__ __forceinline__ float sanit(float v) {
    if (isnan(v)) return 0.f;
    if (isinf(v)) return v > 0.f ? 1e4f : -1e4f;
    return v;
}

__device__ __forceinline__ uint32_t smem_u32(const void* p) {
    uint32_t a;
    asm("{ .reg .u64 t; cvta.to.shared.u64 t, %1; cvt.u32.u64 %0, t; }"
        : "=r"(a) : "l"(p));
    return a;
}

__device__ __forceinline__ void cpa16(uint32_t dst, const void* src) {
    asm volatile("cp.async.cg.shared.global [%0], [%1], 16;\n"
                 :: "r"(dst), "l"(src) : "memory");
}

__device__ __forceinline__ void ldm_x4(unsigned* r, uint32_t addr) {
    asm volatile("ldmatrix.sync.aligned.m8n8.x4.shared.b16 {%0,%1,%2,%3}, [%4];"
                 : "=r"(r[0]), "=r"(r[1]), "=r"(r[2]), "=r"(r[3]) : "r"(addr));
}

__device__ __forceinline__ void mma_f16(float* d, const unsigned* a,
                                        unsigned b0, unsigned b1) {
    asm volatile(
        "mma.sync.aligned.m16n8k16.row.col.f32.f16.f16.f32 "
        "{%0,%1,%2,%3}, {%4,%5,%6,%7}, {%8,%9}, {%0,%1,%2,%3};"
        : "+f"(d[0]), "+f"(d[1]), "+f"(d[2]), "+f"(d[3])
        : "r"(a[0]), "r"(a[1]), "r"(a[2]), "r"(a[3]), "r"(b0), "r"(b1));
}

// fast softplus: max(v,0) + log(1 + exp(-|v|)); |abs err| ~5e-7
__device__ __forceinline__ float softplus_f(float v) {
    float p = __expf(-fabsf(v));
    return fmaxf(v, 0.f) + __logf(1.f + p);
}

// ---------------- all-weights fp32 -> fp16 (one kernel, float4) --------------
#define NQ0 (2*DI*DM/4)
#define NQ1 (96*DI/4)
#define NQ2 (DI*DTR/4)
#define NQ3 (DM*DI/4)
__global__ void wconv_kernel(const float* __restrict__ w0, const float* __restrict__ w1,
                             const float* __restrict__ w2, const float* __restrict__ w3) {
    int i = blockIdx.x * blockDim.x + threadIdx.x;
    const float* s; __half* d; int j = i;
    if (j < NQ0) { s = w0; d = h_inw; }
    else { j -= NQ0;
        if (j < NQ1) { s = w1; d = h_xpw; }
        else { j -= NQ1;
            if (j < NQ2) { s = w2; d = h_dtw; }
            else { j -= NQ2; if (j >= NQ3) return; s = w3; d = h_opw; }
        }
    }
    float4 v = ((const float4*)s)[j];
    __half2 a = __floats2half2_rn(v.x, v.y);
    __half2 b = __floats2half2_rn(v.z, v.w);
    ((__half2*)d)[2 * j]     = a;
    ((__half2*)d)[2 * j + 1] = b;
}

// x_proj dt rows (96-stride fp32) -> packed 64-wide half
__global__ void dt2h_kernel() {
    int i = blockIdx.x * blockDim.x + threadIdx.x;   // quad over BL*64
    if (i >= BL * 16) return;
    int r = i >> 4, c = (i & 15) * 4;
    float4 v = *(const float4*)&g_xdbl[(size_t)r * 96 + c];
    __half2 a = __floats2half2_rn(v.x, v.y);
    __half2 b = __floats2half2_rn(v.z, v.w);
    *(__half2*)&g_dt_h[(size_t)r * 64 + c]     = a;
    *(__half2*)&g_dt_h[(size_t)r * 64 + c + 2] = b;
}

// ---------------- LayerNorm --------------------------------------------------
__global__ void ln_kernel(const float* __restrict__ x,
                          const float* __restrict__ g,
                          const float* __restrict__ b) {
    int row = blockIdx.x;
    int tid = threadIdx.x;
    const float* xr = x + (size_t)row * DM;
    float v[4];
    float s = 0.f, s2 = 0.f;
#pragma unroll
    for (int i = 0; i < 4; i++) {
        float t = sanit(xr[tid + i * 256]);
        v[i] = t; s += t; s2 += t * t;
    }
#pragma unroll
    for (int o = 16; o; o >>= 1) {
        s  += __shfl_xor_sync(0xffffffffu, s,  o);
        s2 += __shfl_xor_sync(0xffffffffu, s2, o);
    }
    __shared__ float ss[8], ss2[8], smu, srs;
    int w = tid >> 5, ln = tid & 31;
    if (ln == 0) { ss[w] = s; ss2[w] = s2; }
    __syncthreads();
    if (tid == 0) {
        float a = 0.f, a2 = 0.f;
#pragma unroll
        for (int i = 0; i < 8; i++) { a += ss[i]; a2 += ss2[i]; }
        float mu = a / DM;
        float var = fmaxf(a2 / DM - mu * mu, 0.f);
        smu = mu;
        srs = rsqrtf(var + 1e-5f);
    }
    __syncthreads();
    float mu = smu, rs = srs;
#pragma unroll
    for (int i = 0; i < 4; i++) {
        int c = tid + i * 256;
        g_xn_h[(size_t)row * DM + c] =
            __float2half_rn((v[i] - mu) * rs * g[c] + b[c]);
    }
}

// ---------------- fp16 HMMA GEMM: C[M,N] = A[M,K] * B[N,K]^T -----------------
// epi: 0 f32 store, 1 bias+softplus f32, 2 sanitize+residual f32,
//      3 atomicAdd f32 (split-K), 4 plain fp16 store.
__global__ void __launch_bounds__(256, 2)
gemm_hf(const __half* __restrict__ A, int lda,
        const __half* __restrict__ Bw, int ldb,
        void* __restrict__ Cv, int N, int K, int epi,
        const float* __restrict__ bias, const float* __restrict__ res) {
    extern __shared__ __half sm[];
    const int tid  = threadIdx.x;
    const int lane = tid & 31;
    const int w    = tid >> 5;
    const int wm   = (w >> 2) * 64;
    const int wn   = (w & 3) * 32;
    const int bm   = blockIdx.y * 128;
    const int bn   = blockIdx.x * 128;
    const int NC   = K / CK;

    A  += (size_t)blockIdx.z * K;
    Bw += (size_t)blockIdx.z * K;

    const uint32_t smb = smem_u32(sm);

    float acc[4][4][4];
#pragma unroll
    for (int i = 0; i < 4; i++)
#pragma unroll
        for (int j = 0; j < 4; j++)
#pragma unroll
            for (int r = 0; r < 4; r++) acc[i][j][r] = 0.f;

    const int frow = tid >> 3, fseg = tid & 7;
    auto fill = [&](int c) {
        if (c < NC) {
            const int slot = c % STG;
            const int k0   = c * CK;
            const uint32_t abase = smb + (uint32_t)slot * 32768u;
            const uint32_t bbase = abase + 16384u;
#pragma unroll
            for (int i = 0; i < 4; i++) {
                int row = frow + i * 32;
                uint32_t dw = (uint32_t)row * 128u +
                              (((uint32_t)fseg * 16u) ^ (((uint32_t)row & 7u) << 4));
                cpa16(abase + dw, A + (size_t)(bm + row) * lda + k0 + fseg * 8);
                int br = bn + row; if (br > N - 1) br = N - 1;
                cpa16(bbase + dw, Bw + (size_t)br * ldb + k0 + fseg * 8);
            }
        }
        asm volatile("cp.async.commit_group;" ::: "memory");
    };

    fill(0);
    fill(1);

    const int rowin = lane & 7;
    const int gb0   = (lane >> 3) & 1;
    const int gb1   = lane >> 4;
    uint32_t abaseA[4], xrA[4];
#pragma unroll
    for (int im = 0; im < 4; im++) {
        int rowA = wm + im * 16 + gb0 * 8 + rowin;
        abaseA[im] = (uint32_t)rowA * 128u;
        xrA[im]    = ((uint32_t)rowA & 7u) << 4;
    }
    uint32_t abaseB[2], xrB[2];
#pragma unroll
    for (int jp = 0; jp < 2; jp++) {
        int rowB = wn + jp * 16 + gb1 * 8 + rowin;
        abaseB[jp] = (uint32_t)rowB * 128u;
        xrB[jp]    = ((uint32_t)rowB & 7u) << 4;
    }
    const uint32_t kA_off = (uint32_t)gb1 * 16u;
    const uint32_t kB_off = (uint32_t)gb0 * 16u;

    for (int c = 0; c < NC; c++) {
        asm volatile("cp.async.wait_group 1;" ::: "memory");
        __syncthreads();
        fill(c + 2);

        const int slot = c % STG;
        const uint32_t ab = smb + (uint32_t)slot * 32768u;
        const uint32_t bb = ab + 16384u;
#pragma unroll
        for (int ks = 0; ks < 4; ks++) {
            const uint32_t kbA = (uint32_t)ks * 32u + kA_off;
            const uint32_t kbB = (uint32_t)ks * 32u + kB_off;
            unsigned a[4][4], bp[2][4];
#pragma unroll
            for (int im = 0; im < 4; im++)
                ldm_x4(a[im], ab + abaseA[im] + (kbA ^ xrA[im]));
#pragma unroll
            for (int jp = 0; jp < 2; jp++)
                ldm_x4(bp[jp], bb + abaseB[jp] + (kbB ^ xrB[jp]));
#pragma unroll
            for (int im = 0; im < 4; im++) {
#pragma unroll
                for (int jp = 0; jp < 2; jp++) {
                    mma_f16(acc[im][2 * jp],     a[im], bp[jp][0], bp[jp][1]);
                    mma_f16(acc[im][2 * jp + 1], a[im], bp[jp][2], bp[jp][3]);
                }
            }
        }
    }

    float* Cf = (float*)Cv;
    __half* Ch = (__half*)Cv;
    const int t  = lane & 3;
    const int r8 = lane >> 2;
#pragma unroll
    for (int im = 0; im < 4; im++) {
#pragma unroll
        for (int jn = 0; jn < 4; jn++) {
            int m0 = bm + wm + im * 16 + r8;
            int n0 = bn + wn + jn * 8 + t * 2;
            if (n0 >= N) continue;
#pragma unroll
            for (int half = 0; half < 2; half++) {
                int m = m0 + half * 8;
                float v0 = acc[im][jn][half * 2 + 0];
                float v1 = acc[im][jn][half * 2 + 1];
                if (epi == 4) {
                    *(__half2*)&Ch[(size_t)m * N + n0] = __floats2half2_rn(v0, v1);
                    continue;
                } else if (epi == 1) {
                    v0 = softplus_f(v0 + bias[n0]);
                    v1 = softplus_f(v1 + bias[n0 + 1]);
                } else if (epi == 2) {
                    v0 = sanit(sanit(v0) + res[(size_t)m * N + n0]);
                    v1 = sanit(sanit(v1) + res[(size_t)m * N + n0 + 1]);
                } else if (epi == 3) {
                    atomicAdd(&Cf[(size_t)m * N + n0],     v0);
                    atomicAdd(&Cf[(size_t)m * N + n0 + 1], v1);
                    continue;
                }
                *(float2*)&Cf[(size_t)m * N + n0] = make_float2(v0, v1);
            }
        }
    }
}

// ---------------- causal depthwise conv (k=4) + SiLU, smem tiled -------------
// block: 256 threads; tile 64 timesteps x 64 channels. grid (BL/CT, DI/64).
__global__ void __launch_bounds__(256)
conv2_kernel(const float* __restrict__ cw, const float* __restrict__ cb) {
    __shared__ __half sx[(CT + 3) * 64];
    const int tid = threadIdx.x;
    const int r0  = blockIdx.x * CT;
    const int c0  = blockIdx.y * 64;
    const int l0  = r0 & (L_ - 1);

    // load halo tile: rows r0-3 .. r0+63, 64 channels (16B segments)
    for (int seg = tid; seg < (CT + 3) * 8; seg += 256) {
        int i  = seg >> 3;
        int s8 = (seg & 7) * 8;
        uint4 v = make_uint4(0, 0, 0, 0);
        if (i >= 3 || l0 > 0) {
            int g = r0 - 3 + i;
            v = *(const uint4*)&g_xz_h[(size_t)g * (2 * DI) + c0 + s8];
        }
        *(uint4*)&sx[i * 64 + s8] = v;
    }
    __syncthreads();

    const int c2 = (tid & 31) * 2;
    const int d  = c0 + c2;
    float w0[4], w1[4];
#pragma unroll
    for (int k = 0; k < 4; k++) { w0[k] = cw[d * 4 + k]; w1[k] = cw[(d + 1) * 4 + k]; }
    const float b0 = cb[d], b1 = cb[d + 1];

#pragma unroll
    for (int ii = 0; ii < 8; ii++) {
        int j = (tid >> 5) + ii * 8;             // local output row
        float a0 = b0, a1 = b1;
#pragma unroll
        for (int k = 0; k < 4; k++) {
            float2 f = __half22float2(*(const __half2*)&sx[(j + k) * 64 + c2]);
            a0 = fmaf(f.x, w0[k], a0);
            a1 = fmaf(f.y, w1[k], a1);
        }
        a0 = a0 / (1.f + __expf(-a0));
        a1 = a1 / (1.f + __expf(-a1));
        *(__half2*)&g_u_h[(size_t)(r0 + j) * DI + d] = __floats2half2_rn(a0, a1);
    }
}

// ---------------- selective scan v3: 2 states/lane ---------------------------
__global__ void __launch_bounds__(256)
scan3_kernel(const float* __restrict__ A_log, const float* __restrict__ D_skip) {
    extern __shared__ char smc[];
    float*  sdp = (float*)(smc);
    __half* sup = (__half*)(smc + 16384);
    __half* szp = (__half*)(smc + 24576);
    float*  sBp = (float*)(smc + 32768);
    float*  sCp = (float*)(smc + 40960);
    float*  syp = (float*)(smc + 49152);

    const int tid = threadIdx.x;
    const int s   = tid & 7;
    const int dl  = tid >> 3;
    const int d0  = blockIdx.x * 32;
    const int b   = blockIdx.y;
    const int d   = d0 + dl;

    const float An0 = -__expf(A_log[d * DS + 2 * s]);
    const float An1 = -__expf(A_log[d * DS + 2 * s + 1]);
    const float dAn = An1 - An0;
    const float Dv  = D_skip[d];
    float h0 = 0.f, h1 = 0.f;
    const size_t rb = (size_t)b * L_;

    const uint32_t a_sd = smem_u32(sdp);
    const uint32_t a_su = smem_u32(sup);
    const uint32_t a_sz = smem_u32(szp);
    const uint32_t a_sB = smem_u32(sBp);
    const uint32_t a_sC = smem_u32(sCp);

    auto prefetch = [&](int tile, int buf) {
        size_t r0 = rb + (size_t)tile * TT;
#pragma unroll
        for (int rep = 0; rep < 2; rep++) {
            int seg = tid + rep * 256;
            int row = seg >> 3, c4 = (seg & 7) * 4;
            cpa16(a_sd + (uint32_t)(buf * 2048 + row * 32 + c4) * 4,
                  g_delta + (r0 + row) * DI + d0 + c4);
        }
        {
            int row = tid >> 2, ch = (tid & 3) * 8;
            cpa16(a_su + (uint32_t)(buf * 2048 + row * 32 + ch) * 2,
                  g_u_h + (r0 + row) * DI + d0 + ch);
        }
        {
            int row = tid >> 2, ch = (tid & 3) * 8;
            cpa16(a_sz + (uint32_t)(buf * 2048 + row * 32 + ch) * 2,
                  g_xz_h + (r0 + row) * (2 * DI) + DI + d0 + ch);
        }
        {
            int row = tid >> 2, cf = (tid & 3) * 4;
            cpa16(a_sB + (uint32_t)(buf * 1024 + row * 16 + cf) * 4,
                  g_xdbl + (r0 + row) * 96 + 64 + cf);
        }
        {
            int row = tid >> 2, cf = (tid & 3) * 4;
            cpa16(a_sC + (uint32_t)(buf * 1024 + row * 16 + cf) * 4,
                  g_xdbl + (r0 + row) * 96 + 80 + cf);
        }
        asm volatile("cp.async.commit_group;" ::: "memory");
    };

    prefetch(0, 0);
    const int NT = L_ / TT;
    for (int tile = 0; tile < NT; tile++) {
        const int buf = tile & 1;
        if (tile + 1 < NT) {
            prefetch(tile + 1, buf ^ 1);
            asm volatile("cp.async.wait_group 1;" ::: "memory");
        } else {
            asm volatile("cp.async.wait_group 0;" ::: "memory");
        }
        __syncthreads();

        const float*  pd = sdp + buf * 2048;
        const __half* pu = sup + buf * 2048;
        const __half* pz = szp + buf * 2048;
        const float*  pB = sBp + buf * 1024;
        const float*  pC = sCp + buf * 1024;
#pragma unroll 4
        for (int t = 0; t < TT; t++) {
            float dt = pd[t * 32 + dl];
            float ut = __half2float(pu[t * 32 + dl]);
            float2 Bt = *(const float2*)&pB[t * 16 + 2 * s];
            float2 Ct = *(const float2*)&pC[t * 16 + 2 * s];
            float e0 = __expf(dt * An0);
            float q  = __expf(dt * dAn);
            float du = dt * ut;
            h0 = fmaf(e0,     h0, du * Bt.x);
            h1 = fmaf(e0 * q, h1, du * Bt.y);
            float p = fmaf(h1, Ct.y, h0 * Ct.x);
            p += __shfl_xor_sync(0xffffffffu, p, 1);
            p += __shfl_xor_sync(0xffffffffu, p, 2);
            p += __shfl_xor_sync(0xffffffffu, p, 4);
            if (s == 0) {
                float z  = __half2float(pz[t * 32 + dl]);
                float sg = z / (1.f + __expf(-z));
                syp[t * 32 + dl] = (p + ut * Dv) * sg;
            }
        }
        __syncthreads();

        {
            int row = tid >> 2, col = (tid & 3) * 8;
            float4 v0 = *(const float4*)&syp[row * 32 + col];
            float4 v1 = *(const float4*)&syp[row * 32 + col + 4];
            __half2 o0 = __floats2half2_rn(v0.x, v0.y);
            __half2 o1 = __floats2half2_rn(v0.z, v0.w);
            __half2 o2 = __floats2half2_rn(v1.x, v1.y);
            __half2 o3 = __floats2half2_rn(v1.z, v1.w);
            uint4 pk = make_uint4(*(unsigned*)&o0, *(unsigned*)&o1,
                                  *(unsigned*)&o2, *(unsigned*)&o3);
            *(uint4*)&g_y_h[(rb + (size_t)tile * TT + row) * DI + d0 + col] = pk;
        }
    }
}

// ---------------- launch -----------------------------------------------------
extern "C" void kernel_launch(void* const* d_in, const int* in_sizes, int n_in,
                              void* d_out, int out_size) {
    const float* x         = (const float*)d_in[0];
    const float* ln_g      = (const float*)d_in[1];
    const float* ln_b      = (const float*)d_in[2];
    const float* in_proj_w = (const float*)d_in[3];
    const float* conv_w    = (const float*)d_in[4];
    const float* conv_b    = (const float*)d_in[5];
    const float* x_proj_w  = (const float*)d_in[6];
    const float* dt_proj_w = (const float*)d_in[7];
    const float* dt_proj_b = (const float*)d_in[8];
    const float* A_log     = (const float*)d_in[9];
    const float* D_skip    = (const float*)d_in[10];
    const float* out_proj_w= (const float*)d_in[11];
    float* out = (float*)d_out;

    float *p_xdbl, *p_delta;
    __half *p_xnh, *p_xzh, *p_uh, *p_yh, *p_dth, *p_inw, *p_xpw, *p_dtw, *p_opw;
    cudaGetSymbolAddress((void**)&p_xdbl,  g_xdbl);
    cudaGetSymbolAddress((void**)&p_delta, g_delta);
    cudaGetSymbolAddress((void**)&p_xnh,   g_xn_h);
    cudaGetSymbolAddress((void**)&p_xzh,   g_xz_h);
    cudaGetSymbolAddress((void**)&p_uh,    g_u_h);
    cudaGetSymbolAddress((void**)&p_yh,    g_y_h);
    cudaGetSymbolAddress((void**)&p_dth,   g_dt_h);
    cudaGetSymbolAddress((void**)&p_inw,   h_inw);
    cudaGetSymbolAddress((void**)&p_xpw,   h_xpw);
    cudaGetSymbolAddress((void**)&p_dtw,   h_dtw);
    cudaGetSymbolAddress((void**)&p_opw,   h_opw);

    const int SMEM_GB = STG * 32768;        // 96 KB
    const int SMEM_SC = 57344;              // 56 KB
    cudaFuncSetAttribute(gemm_hf, cudaFuncAttributeMaxDynamicSharedMemorySize,
                         SMEM_GB);
    cudaFuncSetAttribute(scan3_kernel, cudaFuncAttributeMaxDynamicSharedMemorySize,
                         SMEM_SC);

    // 0. all weights fp32 -> fp16 (single kernel)
    const int NQ = NQ0 + NQ1 + NQ2 + NQ3;
    wconv_kernel<<<(NQ + 255) / 256, 256>>>(in_proj_w, x_proj_w, dt_proj_w,
                                            out_proj_w);

    // 1. layernorm -> fp16 xn
    ln_kernel<<<BL, 256>>>(x, ln_g, ln_b);

    // 2. in_proj -> fp16 xz
    gemm_hf<<<dim3(32, 32), 256, SMEM_GB>>>(p_xnh, DM, p_inw, DM, p_xzh,
                                            2 * DI, DM, 4, nullptr, nullptr);

    // 3. depthwise causal conv + silu -> fp16 u (smem tiled)
    conv2_kernel<<<dim3(BL / CT, DI / 64), 256>>>(conv_w, conv_b);

    // 4. x_proj (split-K x8, atomic fp32)
    cudaMemsetAsync(p_xdbl, 0, (size_t)BL * 96 * sizeof(float));
    gemm_hf<<<dim3(1, 32, 8), 256, SMEM_GB>>>(p_uh, DI, p_xpw, DI, p_xdbl,
                                              96, DI / 8, 3, nullptr, nullptr);
    dt2h_kernel<<<(BL * 16) / 256, 256>>>();

    // 5. dt_proj + softplus -> fp32 delta
    gemm_hf<<<dim3(16, 32), 256, SMEM_GB>>>(p_dth, DTR, p_dtw, DTR, p_delta,
                                            DI, DTR, 1, dt_proj_b, nullptr);

    // 6. selective scan + D-skip + silu(z) gate -> fp16 y
    scan3_kernel<<<dim3(DI / 32, B_), 256, SMEM_SC>>>(A_log, D_skip);

    // 7. out_proj + residual(x) + sanitize -> out
    gemm_hf<<<dim3(8, 32), 256, SMEM_GB>>>(p_yh, DI, p_opw, DI, out,
                                           DM, DI, 2, nullptr, x);
}